// round 12
// baseline (speedup 1.0000x reference)
#include <cuda_runtime.h>
#include <cstdint>

#define BSZ 4
#define LQ  512
#define LK  2048
#define DM  1024
#define NH  16
#define DK  64
#define VOCAB_B 900

// ---------------- scratch (static device memory; no runtime alloc) ----------
__device__ float g_Qp[BSZ * LQ * DM];
__device__ float g_Kp[BSZ * LK * DM];
__device__ float g_Vt[BSZ * DM * LK];                  // V projected+transposed
__device__ float g_Ao[BSZ * LQ * DM];
__device__ unsigned short g_bm[BSZ * LQ * LK];         // packed b_idx|mask<<15

// ---------------- PTX helpers ----------------------------------------------
__device__ __forceinline__ uint32_t s_u32(const void* p) {
    uint32_t a;
    asm("{.reg .u64 t; cvta.to.shared.u64 t, %1; cvt.u32.u64 %0, t;}"
        : "=r"(a) : "l"(p));
    return a;
}

__device__ __forceinline__ float rtf32(float x) {
    uint32_t u = __float_as_uint(x);
    asm("cvt.rna.tf32.f32 %0,%0;" : "+r"(u));
    return __uint_as_float(u);
}

#define LDSM4(R0,R1,R2,R3,ADDR) \
    asm volatile("ldmatrix.sync.aligned.m8n8.x4.shared.b16 {%0,%1,%2,%3},[%4];" \
        : "=r"(R0),"=r"(R1),"=r"(R2),"=r"(R3) : "r"(ADDR))

#define CVT_TF32(T) asm volatile("cvt.rna.tf32.f32 %0,%0;" : "+r"(T))

#define MMA_TF32(D,A,B0,B1) \
    asm volatile("mma.sync.aligned.m16n8k8.row.col.f32.tf32.tf32.f32 " \
        "{%0,%1,%2,%3},{%4,%5,%6,%7},{%8,%9},{%0,%1,%2,%3};" \
        : "+f"(D[0]),"+f"(D[1]),"+f"(D[2]),"+f"(D[3]) \
        : "r"(A[0]),"r"(A[1]),"r"(A[2]),"r"(A[3]),"r"(B0),"r"(B1))

#define CP16(DST,SRC) \
    asm volatile("cp.async.cg.shared.global [%0],[%1],16;" :: "r"(DST),"l"(SRC))
#define CPCOMMIT  asm volatile("cp.async.commit_group;")
#define CPWAIT0   asm volatile("cp.async.wait_group 0;")
#define CPWAIT1   asm volatile("cp.async.wait_group 1;")

// ============================================================================
// pack b_idx + mask -> uint16 (idx | mask<<15), 4x ILP grid-strided
// ============================================================================
__device__ __forceinline__ ushort4 pack4(int4 ix, int4 mk) {
    ushort4 o;
    o.x = (unsigned short)(ix.x | (mk.x << 15));
    o.y = (unsigned short)(ix.y | (mk.y << 15));
    o.z = (unsigned short)(ix.z | (mk.z << 15));
    o.w = (unsigned short)(ix.w | (mk.w << 15));
    return o;
}
__global__ __launch_bounds__(256) void pack_bm_kernel(
    const int4* __restrict__ b_idx, const int4* __restrict__ mask,
    ushort4* __restrict__ bm, int n4)
{
    const int s = gridDim.x * 256;
    int i = blockIdx.x * 256 + threadIdx.x;
    if (i + 3 * s < n4) {
        int4 a0 = b_idx[i],         a1 = b_idx[i + s],
             a2 = b_idx[i + 2 * s], a3 = b_idx[i + 3 * s];
        int4 m0 = mask[i],          m1 = mask[i + s],
             m2 = mask[i + 2 * s],  m3 = mask[i + 3 * s];
        bm[i]         = pack4(a0, m0);
        bm[i + s]     = pack4(a1, m1);
        bm[i + 2 * s] = pack4(a2, m2);
        bm[i + 3 * s] = pack4(a3, m3);
    } else {
        for (; i < n4; i += s) bm[i] = pack4(b_idx[i], mask[i]);
    }
}

// ============================================================================
// tf32 GEMM: C = A @ B^T + bias. CTA 128x128, 4 warps, warp 64x64,
// BK=32, 2-deep cp.async pipeline (round-10 proven), 2 CTAs/SM.
// CVTA/CVTB: round frags in-loop. RND: round outputs.
// TRANSV: write transposed to Vt[b][n][m%LK] via smem.
// ============================================================================
template<int CVTA, int CVTB, int RND, int TRANSV>
__global__ __launch_bounds__(128, 2) void gemm_bt_tf32(
    const float* __restrict__ A, const float* __restrict__ B,
    const float* __restrict__ bias, float* __restrict__ C,
    int M, int N, int K)
{
    extern __shared__ float smem[];
    const uint32_t sbase = s_u32(smem);
    const int tid = threadIdx.x;
    const int m0 = blockIdx.y * 128, n0 = blockIdx.x * 128;
    const int l  = tid & 31, w = tid >> 5;
    const int mw = (w >> 1) * 64, nw = (w & 1) * 64;
    const int lrow = l & 15, lq = l >> 4, lx = l & 7;

    float acc[4][8][4];
#pragma unroll
    for (int i = 0; i < 4; i++)
#pragma unroll
        for (int j = 0; j < 8; j++)
#pragma unroll
            for (int r = 0; r < 4; r++) acc[i][j][r] = 0.f;

    const int NIT = K >> 5;

#define STAGE_G(IT, BUF) do {                                                  \
    uint32_t sA_ = sbase + (BUF) * 32768;                                      \
    uint32_t sB_ = sA_ + 16384;                                                \
    const float* Ag_ = A + (size_t)(m0) * K + (IT) * 32;                       \
    const float* Bg_ = B + (size_t)(n0) * K + (IT) * 32;                       \
    _Pragma("unroll")                                                          \
    for (int i_ = 0; i_ < 8; i_++) {                                           \
        int gi_ = tid + i_ * 128;                                              \
        int r_ = gi_ >> 3, g_ = gi_ & 7;                                       \
        CP16(sA_ + r_ * 128 + (((g_ ^ (r_ & 7)) << 4)),                        \
             Ag_ + (size_t)r_ * K + g_ * 4);                                   \
    }                                                                          \
    _Pragma("unroll")                                                          \
    for (int i_ = 0; i_ < 8; i_++) {                                           \
        int gi_ = tid + i_ * 128;                                              \
        int r_ = gi_ >> 3, g_ = gi_ & 7;                                       \
        CP16(sB_ + r_ * 128 + (((g_ ^ (r_ & 7)) << 4)),                        \
             Bg_ + (size_t)r_ * K + g_ * 4);                                   \
    }                                                                          \
} while (0)

    STAGE_G(0, 0);
    CPCOMMIT;

    int buf = 0;
    for (int it = 0; it < NIT; ++it) {
        if (it + 1 < NIT) { STAGE_G(it + 1, buf ^ 1); CPCOMMIT; CPWAIT1; }
        else              { CPWAIT0; }
        __syncthreads();

        const uint32_t sA = sbase + buf * 32768;
        const uint32_t sB = sA + 16384;
        const uint32_t aAdr0 = sA + (mw + lrow) * 128;
        const uint32_t bAdr0 = sB + (nw + (l & 7)) * 128;

#pragma unroll
        for (int s = 0; s < 4; s += 2) {
            uint32_t bfr[8][4];
#pragma unroll
            for (int nf = 0; nf < 8; nf++) {
                uint32_t ad = bAdr0 + nf * 1024 +
                              (((2 * s + ((l >> 3) & 3)) ^ lx) << 4);
                LDSM4(bfr[nf][0], bfr[nf][1], bfr[nf][2], bfr[nf][3], ad);
                if (CVTB) {
                    CVT_TF32(bfr[nf][0]); CVT_TF32(bfr[nf][1]);
                    CVT_TF32(bfr[nf][2]); CVT_TF32(bfr[nf][3]);
                }
            }
#pragma unroll
            for (int ss = 0; ss < 2; ss++) {
                uint32_t a[4][4];
#pragma unroll
                for (int mf = 0; mf < 4; mf++) {
                    uint32_t ad = aAdr0 + mf * 2048 +
                                  (((2 * (s + ss) + lq) ^ lx) << 4);
                    LDSM4(a[mf][0], a[mf][1], a[mf][2], a[mf][3], ad);
                    if (CVTA) {
                        CVT_TF32(a[mf][0]); CVT_TF32(a[mf][1]);
                        CVT_TF32(a[mf][2]); CVT_TF32(a[mf][3]);
                    }
                }
#pragma unroll
                for (int mf = 0; mf < 4; mf++)
#pragma unroll
                    for (int nf = 0; nf < 8; nf++)
                        MMA_TF32(acc[mf][nf], a[mf], bfr[nf][2 * ss], bfr[nf][2 * ss + 1]);
            }
        }
        __syncthreads();
        buf ^= 1;
    }
#undef STAGE_G

    if (TRANSV) {
        // stage rounded acc+bias as [n][m] (pitch 132), write Vt coalesced
        __syncthreads();
#pragma unroll
        for (int mf = 0; mf < 4; mf++) {
            int mloc = mw + mf * 16 + (l >> 2);
#pragma unroll
            for (int nf = 0; nf < 8; nf++) {
                int nloc = nw + nf * 8 + (l & 3) * 2;
                float2 bb = *(const float2*)&bias[n0 + nloc];
                smem[(nloc)     * 132 + mloc]     = rtf32(acc[mf][nf][0] + bb.x);
                smem[(nloc + 1) * 132 + mloc]     = rtf32(acc[mf][nf][1] + bb.y);
                smem[(nloc)     * 132 + mloc + 8] = rtf32(acc[mf][nf][2] + bb.x);
                smem[(nloc + 1) * 132 + mloc + 8] = rtf32(acc[mf][nf][3] + bb.y);
            }
        }
        __syncthreads();
        const int bb_ = m0 / LK;
        const int kb_ = m0 % LK;
#pragma unroll
        for (int i = 0; i < 32; i++) {
            int n = w * 32 + i;
            float4 vv = *(const float4*)&smem[n * 132 + 4 * l];
            *(float4*)&C[((size_t)(bb_ * DM + n0 + n)) * LK + kb_ + 4 * l] = vv;
        }
    } else {
#pragma unroll
        for (int mf = 0; mf < 4; mf++) {
            int row = m0 + mw + mf * 16 + (l >> 2);
#pragma unroll
            for (int nf = 0; nf < 8; nf++) {
                int col = n0 + nw + nf * 8 + (l & 3) * 2;
                float2 bb = *(const float2*)&bias[col];
                float2 o0, o1;
                o0.x = acc[mf][nf][0] + bb.x; o0.y = acc[mf][nf][1] + bb.y;
                o1.x = acc[mf][nf][2] + bb.x; o1.y = acc[mf][nf][3] + bb.y;
                if (RND) {
                    o0.x = rtf32(o0.x); o0.y = rtf32(o0.y);
                    o1.x = rtf32(o1.x); o1.y = rtf32(o1.y);
                }
                *(float2*)&C[(size_t)row * N + col]       = o0;
                *(float2*)&C[(size_t)(row + 8) * N + col] = o1;
            }
        }
    }
}

// ============================================================================
// Fused flash attention. CTA: 64 queries, 4 warps, 2 CTAs/SM.
// 2-deep cp.async pipeline (round-10 proven). No online-softmax rescaling:
// scores are O(10) so exp() directly is fp32-safe; masked entries are exact 0.
// Per-lane partial sums; normalize at end (zero-sum guarded).
// ============================================================================
__global__ __launch_bounds__(128, 2) void flash_attn_tf32(
    const float* __restrict__ Qp, const float* __restrict__ Kp,
    const float* __restrict__ Vt, const unsigned short* __restrict__ bm,
    const float* __restrict__ b_table, float* __restrict__ Ao)
{
    extern __shared__ float smem[];
    const uint32_t sb = s_u32(smem);
    const uint32_t sQ = sb;                       // aliased by P after Q consumed
    const uint32_t sKb[2]  = { sb + 16384, sb + 57344 };
    const uint32_t sVb[2]  = { sb + 32768, sb + 73728 };
    const uint32_t sBMb[2] = { sb + 49152, sb + 90112 };
    const uint32_t bmOff[2] = { 49152, 90112 };
    float* btm = smem + 98304 / 4;

    const int tid = threadIdx.x;
    const int h = blockIdx.x, b = blockIdx.z;
    const int m0 = blockIdx.y * 64;
    const int l = tid & 31, w = tid >> 5;
    const int mw = w * 16;
    const int lx = l & 7;

    for (int i = tid; i < VOCAB_B; i += 128) btm[i] = b_table[i * NH + h];

    const float* Qg = Qp + ((size_t)(b * LQ + m0)) * DM + h * DK;
    const float* Kg = Kp + ((size_t)(b * LK)) * DM + h * DK;
    const float* Vg = Vt + ((size_t)(b * DM + h * DK)) * LK;
    const unsigned short* BMg = bm + ((size_t)(b * LQ + m0)) * LK;

#pragma unroll
    for (int i = 0; i < 8; i++) {
        int gi = tid + i * 128;
        int r = gi >> 4, g = gi & 15;
        CP16(sQ + r * 256 + (((g ^ (r & 7)) << 4)), Qg + (size_t)r * DM + g * 4);
    }

#define STAGE_KV(IT, BUF) do {                                                 \
    const float* Ksrc_ = Kg + (size_t)((IT) * 64) * DM;                        \
    const float* Vsrc_ = Vg + (IT) * 64;                                       \
    const unsigned short* Bsrc_ = BMg + (IT) * 64;                             \
    _Pragma("unroll")                                                          \
    for (int i_ = 0; i_ < 8; i_++) {                                           \
        int gi_ = tid + i_ * 128;                                              \
        int r_ = gi_ >> 4, g_ = gi_ & 15;                                      \
        CP16(sKb[BUF] + r_ * 256 + (((g_ ^ (r_ & 7)) << 4)),                   \
             Ksrc_ + (size_t)r_ * DM + g_ * 4);                                \
    }                                                                          \
    _Pragma("unroll")                                                          \
    for (int i_ = 0; i_ < 8; i_++) {                                           \
        int gi_ = tid + i_ * 128;                                              \
        int r_ = gi_ >> 4, g_ = gi_ & 15;                                      \
        CP16(sVb[BUF] + r_ * 256 + (((g_ ^ (r_ & 7)) << 4)),                   \
             Vsrc_ + (size_t)r_ * LK + g_ * 4);                                \
    }                                                                          \
    _Pragma("unroll")                                                          \
    for (int i_ = 0; i_ < 4; i_++) {                                           \
        int gi_ = tid + i_ * 128;                                              \
        int r_ = gi_ >> 3, g_ = gi_ & 7;                                       \
        CP16(sBMb[BUF] + r_ * 128 + (((g_ ^ (r_ & 7)) << 4)),                  \
             Bsrc_ + (size_t)r_ * LK + g_ * 8);                                \
    }                                                                          \
} while (0)

    STAGE_KV(0, 0);
    CPCOMMIT;

    uint32_t aq[8][4];
    float oacc[8][4];
#pragma unroll
    for (int nf = 0; nf < 8; nf++)
#pragma unroll
        for (int r = 0; r < 4; r++) oacc[nf][r] = 0.f;
    float sr0 = 0.f, sr1 = 0.f;          // per-lane partial sums

    const int lr = mw + (l >> 2);
    const uint32_t lrx = (uint32_t)(lr & 7);

    int buf = 0;
    for (int it = 0; it < LK / 64; ++it) {
        if (it + 1 < LK / 64) { STAGE_KV(it + 1, buf ^ 1); CPCOMMIT; CPWAIT1; }
        else                  { CPWAIT0; }
        __syncthreads();

        if (it == 0) {
#pragma unroll
            for (int kg = 0; kg < 8; kg++) {
                uint32_t ad = sQ + (mw + (l & 15)) * 256 +
                              (((2 * kg + (l >> 4)) ^ lx) << 4);
                LDSM4(aq[kg][0], aq[kg][1], aq[kg][2], aq[kg][3], ad);
            }
        }

        // ---- S = Q K^T ----
        float sval[8][4];
#pragma unroll
        for (int nf = 0; nf < 8; nf++)
#pragma unroll
            for (int r = 0; r < 4; r++) sval[nf][r] = 0.f;

#pragma unroll
        for (int s = 0; s < 8; s += 2) {
#pragma unroll
            for (int nf = 0; nf < 8; nf++) {
                uint32_t kb[4];
                uint32_t ad = sKb[buf] + (nf * 8 + lx) * 256 +
                              (((2 * s + ((l >> 3) & 3)) ^ lx) << 4);
                LDSM4(kb[0], kb[1], kb[2], kb[3], ad);
                MMA_TF32(sval[nf], aq[s],     kb[0], kb[1]);
                MMA_TF32(sval[nf], aq[s + 1], kb[2], kb[3]);
            }
        }

        // ---- scale + bias gather + mask + exp (no max subtraction) ----
        {
            const uint32_t base = bmOff[buf] / 4 + lr * 32 + (l & 3);
            const uint32_t* sm32 = (const uint32_t*)smem;
#pragma unroll
            for (int nf = 0; nf < 8; nf++) {
                uint32_t o = base + (((uint32_t)nf ^ lrx) << 2);
                uint32_t e01 = sm32[o];
                uint32_t e23 = sm32[o + 8 * 32];
                uint32_t e0 = e01 & 0xffffu, e1 = e01 >> 16;
                uint32_t e2 = e23 & 0xffffu, e3 = e23 >> 16;
                sval[nf][0] = (e0 & 0x8000u) ? __expf(sval[nf][0] * 0.125f + btm[e0 & 0x3ffu]) : 0.f;
                sval[nf][1] = (e1 & 0x8000u) ? __expf(sval[nf][1] * 0.125f + btm[e1 & 0x3ffu]) : 0.f;
                sval[nf][2] = (e2 & 0x8000u) ? __expf(sval[nf][2] * 0.125f + btm[e2 & 0x3ffu]) : 0.f;
                sval[nf][3] = (e3 & 0x8000u) ? __expf(sval[nf][3] * 0.125f + btm[e3 & 0x3ffu]) : 0.f;
                sr0 += sval[nf][0] + sval[nf][1];
                sr1 += sval[nf][2] + sval[nf][3];
            }
        }

        // ---- P -> per-warp patch (aliases this warp's Q rows) ----
        {
            const uint32_t pb = sQ + w * 4096;
            const int rs0 = l >> 2;
            const uint32_t boff = ((l & 1) << 3);
            __syncwarp();
#pragma unroll
            for (int nf = 0; nf < 8; nf++) {
                int g = nf * 2 + ((l & 3) >> 1);
                uint32_t a0 = pb + rs0 * 256 + (((g ^ rs0) << 4)) + boff;
                uint32_t a1 = pb + (rs0 + 8) * 256 + (((g ^ rs0) << 4)) + boff;
                float2 p0 = { sval[nf][0], sval[nf][1] };
                float2 p1 = { sval[nf][2], sval[nf][3] };
                *(float2*)(smem + ((a0 - sb) >> 2)) = p0;
                *(float2*)(smem + ((a1 - sb) >> 2)) = p1;
            }
            __syncwarp();
        }

        uint32_t pa[8][4];
#pragma unroll
        for (int kg = 0; kg < 8; kg++) {
            uint32_t ad = sQ + w * 4096 + (l & 15) * 256 +
                          (((2 * kg + (l >> 4)) ^ lx) << 4);
            LDSM4(pa[kg][0], pa[kg][1], pa[kg][2], pa[kg][3], ad);
            CVT_TF32(pa[kg][0]); CVT_TF32(pa[kg][1]);
            CVT_TF32(pa[kg][2]); CVT_TF32(pa[kg][3]);
        }

        // ---- O += P V ----
#pragma unroll
        for (int s = 0; s < 8; s += 2) {
#pragma unroll
            for (int nf = 0; nf < 8; nf++) {
                uint32_t bv[4];
                uint32_t ad = sVb[buf] + (nf * 8 + lx) * 256 +
                              (((2 * s + ((l >> 3) & 3)) ^ lx) << 4);
                LDSM4(bv[0], bv[1], bv[2], bv[3], ad);
                MMA_TF32(oacc[nf], pa[s],     bv[0], bv[1]);
                MMA_TF32(oacc[nf], pa[s + 1], bv[2], bv[3]);
            }
        }

        __syncthreads();
        buf ^= 1;
    }
#undef STAGE_KV

    // ---- reduce sums across the 4 lanes sharing each row, write O ----
    {
#pragma unroll
        for (int o = 1; o < 4; o <<= 1) {
            sr0 += __shfl_xor_sync(0xffffffffu, sr0, o);
            sr1 += __shfl_xor_sync(0xffffffffu, sr1, o);
        }
        const float i0 = (sr0 > 0.f) ? 1.f / sr0 : 0.f;
        const float i1 = (sr1 > 0.f) ? 1.f / sr1 : 0.f;
        const int r0 = m0 + mw + (l >> 2);
#pragma unroll
        for (int nf = 0; nf < 8; nf++) {
            int col = h * DK + nf * 8 + (l & 3) * 2;
            float2 o0 = { rtf32(oacc[nf][0] * i0), rtf32(oacc[nf][1] * i0) };
            float2 o1 = { rtf32(oacc[nf][2] * i1), rtf32(oacc[nf][3] * i1) };
            *(float2*)&Ao[((size_t)(b * LQ + r0)) * DM + col]     = o0;
            *(float2*)&Ao[((size_t)(b * LQ + r0 + 8)) * DM + col] = o1;
        }
    }
}

// ---------------------------------------------------------------------------
extern "C" void kernel_launch(void* const* d_in, const int* in_sizes, int n_in,
                              void* d_out, int out_size)
{
    const float* q       = (const float*)d_in[0];
    const float* k       = (const float*)d_in[1];
    const float* v       = (const float*)d_in[2];
    const int*   b_idx   = (const int*)  d_in[3];
    const int*   mask    = (const int*)  d_in[4];
    const float* Wq      = (const float*)d_in[5];
    const float* bq      = (const float*)d_in[6];
    const float* Wk      = (const float*)d_in[7];
    const float* bk      = (const float*)d_in[8];
    const float* Wv      = (const float*)d_in[9];
    const float* bv      = (const float*)d_in[10];
    const float* Wo      = (const float*)d_in[11];
    const float* bo      = (const float*)d_in[12];
    const float* b_table = (const float*)d_in[13];
    float* out = (float*)d_out;

    void *Qp_, *Kp_, *Vt_, *Ao_, *bm_;
    cudaGetSymbolAddress(&Qp_, g_Qp);
    cudaGetSymbolAddress(&Kp_, g_Kp);
    cudaGetSymbolAddress(&Vt_, g_Vt);
    cudaGetSymbolAddress(&Ao_, g_Ao);
    cudaGetSymbolAddress(&bm_, g_bm);
    float* Qp = (float*)Qp_;
    float* Kp = (float*)Kp_;
    float* Vt = (float*)Vt_;
    float* Ao = (float*)Ao_;
    unsigned short* bm = (unsigned short*)bm_;

    static int attr_set = 0;
    if (!attr_set) {
        cudaFuncSetAttribute((const void*)gemm_bt_tf32<1,1,1,0>, cudaFuncAttributeMaxDynamicSharedMemorySize, 65536);
        cudaFuncSetAttribute((const void*)gemm_bt_tf32<1,1,1,1>, cudaFuncAttributeMaxDynamicSharedMemorySize, 69632);
        cudaFuncSetAttribute((const void*)gemm_bt_tf32<0,1,0,0>, cudaFuncAttributeMaxDynamicSharedMemorySize, 65536);
        cudaFuncSetAttribute((const void*)flash_attn_tf32,       cudaFuncAttributeMaxDynamicSharedMemorySize, 101904);
        attr_set = 1;
    }

    // pack bias/mask (h-invariant; L2-resident for flash)
    const int NB4 = BSZ * LQ * LK / 4;
    pack_bm_kernel<<<1024, 256>>>((const int4*)b_idx, (const int4*)mask, (ushort4*)bm, NB4);

    // projections (frags rounded in-loop; outputs rounded)
    gemm_bt_tf32<1,1,1,0><<<dim3(DM / 128, (BSZ * LQ) / 128), 128, 65536>>>(q, Wq, bq, Qp, BSZ * LQ, DM, DM);
    gemm_bt_tf32<1,1,1,0><<<dim3(DM / 128, (BSZ * LK) / 128), 128, 65536>>>(k, Wk, bk, Kp, BSZ * LK, DM, DM);
    gemm_bt_tf32<1,1,1,1><<<dim3(DM / 128, (BSZ * LK) / 128), 128, 69632>>>(v, Wv, bv, Vt, BSZ * LK, DM, DM);

    // fused attention (h fastest for packed bm L2 reuse)
    flash_attn_tf32<<<dim3(NH, LQ / 64, BSZ), 128, 101904>>>(
        Qp, Kp, Vt, bm, b_table, Ao);

    // output projection (A pre-rounded at flash epilogue; output fp32)
    gemm_bt_tf32<0,1,0,0><<<dim3(DM / 128, (BSZ * LQ) / 128), 128, 65536>>>(Ao, Wo, bo, out, BSZ * LQ, DM, DM);
}

// round 13
// speedup vs baseline: 1.2268x; 1.2268x over previous
#include <cuda_runtime.h>
#include <cstdint>

#define BSZ 4
#define LQ  512
#define LK  2048
#define DM  1024
#define NH  16
#define DK  64
#define VOCAB_B 900

// ---------------- scratch (static device memory; no runtime alloc) ----------
__device__ float g_Qp[BSZ * LQ * DM];
__device__ float g_Kp[BSZ * LK * DM];
__device__ float g_Vt[BSZ * DM * LK];                  // V projected+transposed
__device__ float g_Ao[BSZ * LQ * DM];
__device__ unsigned short g_bm[BSZ * LQ * LK];         // packed b_idx|mask<<15

// ---------------- PTX helpers ----------------------------------------------
__device__ __forceinline__ uint32_t s_u32(const void* p) {
    uint32_t a;
    asm("{.reg .u64 t; cvta.to.shared.u64 t, %1; cvt.u32.u64 %0, t;}"
        : "=r"(a) : "l"(p));
    return a;
}

__device__ __forceinline__ float rtf32(float x) {
    uint32_t u = __float_as_uint(x);
    asm("cvt.rna.tf32.f32 %0,%0;" : "+r"(u));
    return __uint_as_float(u);
}

#define LDSM4(R0,R1,R2,R3,ADDR) \
    asm volatile("ldmatrix.sync.aligned.m8n8.x4.shared.b16 {%0,%1,%2,%3},[%4];" \
        : "=r"(R0),"=r"(R1),"=r"(R2),"=r"(R3) : "r"(ADDR))

#define CVT_TF32(T) asm volatile("cvt.rna.tf32.f32 %0,%0;" : "+r"(T))

#define MMA_TF32(D,A,B0,B1) \
    asm volatile("mma.sync.aligned.m16n8k8.row.col.f32.tf32.tf32.f32 " \
        "{%0,%1,%2,%3},{%4,%5,%6,%7},{%8,%9},{%0,%1,%2,%3};" \
        : "+f"(D[0]),"+f"(D[1]),"+f"(D[2]),"+f"(D[3]) \
        : "r"(A[0]),"r"(A[1]),"r"(A[2]),"r"(A[3]),"r"(B0),"r"(B1))

#define CP16(DST,SRC) \
    asm volatile("cp.async.cg.shared.global [%0],[%1],16;" :: "r"(DST),"l"(SRC))
#define CPCOMMIT  asm volatile("cp.async.commit_group;")
#define CPWAIT0   asm volatile("cp.async.wait_group 0;")
#define CPWAIT1   asm volatile("cp.async.wait_group 1;")

// ============================================================================
// pack b_idx + mask -> uint16 (idx | mask<<15), 4x ILP grid-strided
// ============================================================================
__device__ __forceinline__ ushort4 pack4(int4 ix, int4 mk) {
    ushort4 o;
    o.x = (unsigned short)(ix.x | (mk.x << 15));
    o.y = (unsigned short)(ix.y | (mk.y << 15));
    o.z = (unsigned short)(ix.z | (mk.z << 15));
    o.w = (unsigned short)(ix.w | (mk.w << 15));
    return o;
}
__global__ __launch_bounds__(256) void pack_bm_kernel(
    const int4* __restrict__ b_idx, const int4* __restrict__ mask,
    ushort4* __restrict__ bm, int n4)
{
    const int s = gridDim.x * 256;
    int i = blockIdx.x * 256 + threadIdx.x;
    if (i + 3 * s < n4) {
        int4 a0 = b_idx[i],         a1 = b_idx[i + s],
             a2 = b_idx[i + 2 * s], a3 = b_idx[i + 3 * s];
        int4 m0 = mask[i],          m1 = mask[i + s],
             m2 = mask[i + 2 * s],  m3 = mask[i + 3 * s];
        bm[i]         = pack4(a0, m0);
        bm[i + s]     = pack4(a1, m1);
        bm[i + 2 * s] = pack4(a2, m2);
        bm[i + 3 * s] = pack4(a3, m3);
    } else {
        for (; i < n4; i += s) bm[i] = pack4(b_idx[i], mask[i]);
    }
}

// ============================================================================
// tf32 GEMM: C = A @ B^T + bias. CTA 128x128, 4 warps, warp 64x64,
// BK=32, 2-deep cp.async pipeline, 2 CTAs/SM.
// CVTA/CVTB: round frags in-loop. RND: round outputs.
// TRANSV: write transposed to Vt[b][n][m%LK] via smem.
// ============================================================================
template<int CVTA, int CVTB, int RND, int TRANSV>
__global__ __launch_bounds__(128, 2) void gemm_bt_tf32(
    const float* __restrict__ A, const float* __restrict__ B,
    const float* __restrict__ bias, float* __restrict__ C,
    int M, int N, int K)
{
    extern __shared__ float smem[];
    const uint32_t sbase = s_u32(smem);
    const int tid = threadIdx.x;
    const int m0 = blockIdx.y * 128, n0 = blockIdx.x * 128;
    const int l  = tid & 31, w = tid >> 5;
    const int mw = (w >> 1) * 64, nw = (w & 1) * 64;
    const int lrow = l & 15, lq = l >> 4, lx = l & 7;

    float acc[4][8][4];
#pragma unroll
    for (int i = 0; i < 4; i++)
#pragma unroll
        for (int j = 0; j < 8; j++)
#pragma unroll
            for (int r = 0; r < 4; r++) acc[i][j][r] = 0.f;

    const int NIT = K >> 5;

#define STAGE_G(IT, BUF) do {                                                  \
    uint32_t sA_ = sbase + (BUF) * 32768;                                      \
    uint32_t sB_ = sA_ + 16384;                                                \
    const float* Ag_ = A + (size_t)(m0) * K + (IT) * 32;                       \
    const float* Bg_ = B + (size_t)(n0) * K + (IT) * 32;                       \
    _Pragma("unroll")                                                          \
    for (int i_ = 0; i_ < 8; i_++) {                                           \
        int gi_ = tid + i_ * 128;                                              \
        int r_ = gi_ >> 3, g_ = gi_ & 7;                                       \
        CP16(sA_ + r_ * 128 + (((g_ ^ (r_ & 7)) << 4)),                        \
             Ag_ + (size_t)r_ * K + g_ * 4);                                   \
    }                                                                          \
    _Pragma("unroll")                                                          \
    for (int i_ = 0; i_ < 8; i_++) {                                           \
        int gi_ = tid + i_ * 128;                                              \
        int r_ = gi_ >> 3, g_ = gi_ & 7;                                       \
        CP16(sB_ + r_ * 128 + (((g_ ^ (r_ & 7)) << 4)),                        \
             Bg_ + (size_t)r_ * K + g_ * 4);                                   \
    }                                                                          \
} while (0)

    STAGE_G(0, 0);
    CPCOMMIT;

    int buf = 0;
    for (int it = 0; it < NIT; ++it) {
        if (it + 1 < NIT) { STAGE_G(it + 1, buf ^ 1); CPCOMMIT; CPWAIT1; }
        else              { CPWAIT0; }
        __syncthreads();

        const uint32_t sA = sbase + buf * 32768;
        const uint32_t sB = sA + 16384;
        const uint32_t aAdr0 = sA + (mw + lrow) * 128;
        const uint32_t bAdr0 = sB + (nw + (l & 7)) * 128;

#pragma unroll
        for (int s = 0; s < 4; s += 2) {
            uint32_t bfr[8][4];
#pragma unroll
            for (int nf = 0; nf < 8; nf++) {
                uint32_t ad = bAdr0 + nf * 1024 +
                              (((2 * s + ((l >> 3) & 3)) ^ lx) << 4);
                LDSM4(bfr[nf][0], bfr[nf][1], bfr[nf][2], bfr[nf][3], ad);
                if (CVTB) {
                    CVT_TF32(bfr[nf][0]); CVT_TF32(bfr[nf][1]);
                    CVT_TF32(bfr[nf][2]); CVT_TF32(bfr[nf][3]);
                }
            }
#pragma unroll
            for (int ss = 0; ss < 2; ss++) {
                uint32_t a[4][4];
#pragma unroll
                for (int mf = 0; mf < 4; mf++) {
                    uint32_t ad = aAdr0 + mf * 2048 +
                                  (((2 * (s + ss) + lq) ^ lx) << 4);
                    LDSM4(a[mf][0], a[mf][1], a[mf][2], a[mf][3], ad);
                    if (CVTA) {
                        CVT_TF32(a[mf][0]); CVT_TF32(a[mf][1]);
                        CVT_TF32(a[mf][2]); CVT_TF32(a[mf][3]);
                    }
                }
#pragma unroll
                for (int mf = 0; mf < 4; mf++)
#pragma unroll
                    for (int nf = 0; nf < 8; nf++)
                        MMA_TF32(acc[mf][nf], a[mf], bfr[nf][2 * ss], bfr[nf][2 * ss + 1]);
            }
        }
        __syncthreads();
        buf ^= 1;
    }
#undef STAGE_G

    if (TRANSV) {
        // stage rounded acc+bias as [n][m] (pitch 132), write Vt coalesced
        __syncthreads();
#pragma unroll
        for (int mf = 0; mf < 4; mf++) {
            int mloc = mw + mf * 16 + (l >> 2);
#pragma unroll
            for (int nf = 0; nf < 8; nf++) {
                int nloc = nw + nf * 8 + (l & 3) * 2;
                float2 bb = *(const float2*)&bias[n0 + nloc];
                smem[(nloc)     * 132 + mloc]     = rtf32(acc[mf][nf][0] + bb.x);
                smem[(nloc + 1) * 132 + mloc]     = rtf32(acc[mf][nf][1] + bb.y);
                smem[(nloc)     * 132 + mloc + 8] = rtf32(acc[mf][nf][2] + bb.x);
                smem[(nloc + 1) * 132 + mloc + 8] = rtf32(acc[mf][nf][3] + bb.y);
            }
        }
        __syncthreads();
        const int bb_ = m0 / LK;
        const int kb_ = m0 % LK;
#pragma unroll
        for (int i = 0; i < 32; i++) {
            int n = w * 32 + i;
            float4 vv = *(const float4*)&smem[n * 132 + 4 * l];
            *(float4*)&C[((size_t)(bb_ * DM + n0 + n)) * LK + kb_ + 4 * l] = vv;
        }
    } else {
#pragma unroll
        for (int mf = 0; mf < 4; mf++) {
            int row = m0 + mw + mf * 16 + (l >> 2);
#pragma unroll
            for (int nf = 0; nf < 8; nf++) {
                int col = n0 + nw + nf * 8 + (l & 3) * 2;
                float2 bb = *(const float2*)&bias[col];
                float2 o0, o1;
                o0.x = acc[mf][nf][0] + bb.x; o0.y = acc[mf][nf][1] + bb.y;
                o1.x = acc[mf][nf][2] + bb.x; o1.y = acc[mf][nf][3] + bb.y;
                if (RND) {
                    o0.x = rtf32(o0.x); o0.y = rtf32(o0.y);
                    o1.x = rtf32(o1.x); o1.y = rtf32(o1.y);
                }
                *(float2*)&C[(size_t)row * N + col]       = o0;
                *(float2*)&C[(size_t)(row + 8) * N + col] = o1;
            }
        }
    }
}

// ============================================================================
// Fused flash attention. CTA: 64 queries, 4 warps, 2 CTAs/SM.
// No-max softmax, BRANCHLESS: mask selects the exp ARGUMENT (-1e30 -> exp=0),
// exp runs unconditionally (no divergent MUFU regions).
// ============================================================================
__global__ __launch_bounds__(128, 2) void flash_attn_tf32(
    const float* __restrict__ Qp, const float* __restrict__ Kp,
    const float* __restrict__ Vt, const unsigned short* __restrict__ bm,
    const float* __restrict__ b_table, float* __restrict__ Ao)
{
    extern __shared__ float smem[];
    const uint32_t sb = s_u32(smem);
    const uint32_t sQ = sb;                       // aliased by P after Q consumed
    const uint32_t sKb[2]  = { sb + 16384, sb + 57344 };
    const uint32_t sVb[2]  = { sb + 32768, sb + 73728 };
    const uint32_t sBMb[2] = { sb + 49152, sb + 90112 };
    const uint32_t bmOff[2] = { 49152, 90112 };
    float* btm = smem + 98304 / 4;

    const int tid = threadIdx.x;
    const int h = blockIdx.x, b = blockIdx.z;
    const int m0 = blockIdx.y * 64;
    const int l = tid & 31, w = tid >> 5;
    const int mw = w * 16;
    const int lx = l & 7;

    for (int i = tid; i < VOCAB_B; i += 128) btm[i] = b_table[i * NH + h];

    const float* Qg = Qp + ((size_t)(b * LQ + m0)) * DM + h * DK;
    const float* Kg = Kp + ((size_t)(b * LK)) * DM + h * DK;
    const float* Vg = Vt + ((size_t)(b * DM + h * DK)) * LK;
    const unsigned short* BMg = bm + ((size_t)(b * LQ + m0)) * LK;

#pragma unroll
    for (int i = 0; i < 8; i++) {
        int gi = tid + i * 128;
        int r = gi >> 4, g = gi & 15;
        CP16(sQ + r * 256 + (((g ^ (r & 7)) << 4)), Qg + (size_t)r * DM + g * 4);
    }

#define STAGE_KV(IT, BUF) do {                                                 \
    const float* Ksrc_ = Kg + (size_t)((IT) * 64) * DM;                        \
    const float* Vsrc_ = Vg + (IT) * 64;                                       \
    const unsigned short* Bsrc_ = BMg + (IT) * 64;                             \
    _Pragma("unroll")                                                          \
    for (int i_ = 0; i_ < 8; i_++) {                                           \
        int gi_ = tid + i_ * 128;                                              \
        int r_ = gi_ >> 4, g_ = gi_ & 15;                                      \
        CP16(sKb[BUF] + r_ * 256 + (((g_ ^ (r_ & 7)) << 4)),                   \
             Ksrc_ + (size_t)r_ * DM + g_ * 4);                                \
    }                                                                          \
    _Pragma("unroll")                                                          \
    for (int i_ = 0; i_ < 8; i_++) {                                           \
        int gi_ = tid + i_ * 128;                                              \
        int r_ = gi_ >> 4, g_ = gi_ & 15;                                      \
        CP16(sVb[BUF] + r_ * 256 + (((g_ ^ (r_ & 7)) << 4)),                   \
             Vsrc_ + (size_t)r_ * LK + g_ * 4);                                \
    }                                                                          \
    _Pragma("unroll")                                                          \
    for (int i_ = 0; i_ < 4; i_++) {                                           \
        int gi_ = tid + i_ * 128;                                              \
        int r_ = gi_ >> 3, g_ = gi_ & 7;                                       \
        CP16(sBMb[BUF] + r_ * 128 + (((g_ ^ (r_ & 7)) << 4)),                  \
             Bsrc_ + (size_t)r_ * LK + g_ * 8);                                \
    }                                                                          \
} while (0)

    STAGE_KV(0, 0);
    CPCOMMIT;

    uint32_t aq[8][4];
    float oacc[8][4];
#pragma unroll
    for (int nf = 0; nf < 8; nf++)
#pragma unroll
        for (int r = 0; r < 4; r++) oacc[nf][r] = 0.f;
    float sr0 = 0.f, sr1 = 0.f;          // per-lane partial sums

    const int lr = mw + (l >> 2);
    const uint32_t lrx = (uint32_t)(lr & 7);

    int buf = 0;
    for (int it = 0; it < LK / 64; ++it) {
        if (it + 1 < LK / 64) { STAGE_KV(it + 1, buf ^ 1); CPCOMMIT; CPWAIT1; }
        else                  { CPWAIT0; }
        __syncthreads();

        if (it == 0) {
#pragma unroll
            for (int kg = 0; kg < 8; kg++) {
                uint32_t ad = sQ + (mw + (l & 15)) * 256 +
                              (((2 * kg + (l >> 4)) ^ lx) << 4);
                LDSM4(aq[kg][0], aq[kg][1], aq[kg][2], aq[kg][3], ad);
            }
        }

        // ---- S = Q K^T ----
        float sval[8][4];
#pragma unroll
        for (int nf = 0; nf < 8; nf++)
#pragma unroll
            for (int r = 0; r < 4; r++) sval[nf][r] = 0.f;

#pragma unroll
        for (int s = 0; s < 8; s += 2) {
#pragma unroll
            for (int nf = 0; nf < 8; nf++) {
                uint32_t kb[4];
                uint32_t ad = sKb[buf] + (nf * 8 + lx) * 256 +
                              (((2 * s + ((l >> 3) & 3)) ^ lx) << 4);
                LDSM4(kb[0], kb[1], kb[2], kb[3], ad);
                MMA_TF32(sval[nf], aq[s],     kb[0], kb[1]);
                MMA_TF32(sval[nf], aq[s + 1], kb[2], kb[3]);
            }
        }

        // ---- scale + bias gather + mask (SELECT) then unconditional exp ----
        {
            const uint32_t base = bmOff[buf] / 4 + lr * 32 + (l & 3);
            const uint32_t* sm32 = (const uint32_t*)smem;
#pragma unroll
            for (int nf = 0; nf < 8; nf++) {
                uint32_t o = base + (((uint32_t)nf ^ lrx) << 2);
                uint32_t e01 = sm32[o];
                uint32_t e23 = sm32[o + 8 * 32];
                uint32_t e0 = e01 & 0xffffu, e1 = e01 >> 16;
                uint32_t e2 = e23 & 0xffffu, e3 = e23 >> 16;
                float a0 = (e0 & 0x8000u) ? sval[nf][0] * 0.125f + btm[e0 & 0x3ffu] : -1e30f;
                float a1 = (e1 & 0x8000u) ? sval[nf][1] * 0.125f + btm[e1 & 0x3ffu] : -1e30f;
                float a2 = (e2 & 0x8000u) ? sval[nf][2] * 0.125f + btm[e2 & 0x3ffu] : -1e30f;
                float a3 = (e3 & 0x8000u) ? sval[nf][3] * 0.125f + btm[e3 & 0x3ffu] : -1e30f;
                sval[nf][0] = __expf(a0);
                sval[nf][1] = __expf(a1);
                sval[nf][2] = __expf(a2);
                sval[nf][3] = __expf(a3);
                sr0 += sval[nf][0] + sval[nf][1];
                sr1 += sval[nf][2] + sval[nf][3];
            }
        }

        // ---- P -> per-warp patch (aliases this warp's Q rows) ----
        {
            const uint32_t pb = sQ + w * 4096;
            const int rs0 = l >> 2;
            const uint32_t boff = ((l & 1) << 3);
            __syncwarp();
#pragma unroll
            for (int nf = 0; nf < 8; nf++) {
                int g = nf * 2 + ((l & 3) >> 1);
                uint32_t a0 = pb + rs0 * 256 + (((g ^ rs0) << 4)) + boff;
                uint32_t a1 = pb + (rs0 + 8) * 256 + (((g ^ rs0) << 4)) + boff;
                float2 p0 = { sval[nf][0], sval[nf][1] };
                float2 p1 = { sval[nf][2], sval[nf][3] };
                *(float2*)(smem + ((a0 - sb) >> 2)) = p0;
                *(float2*)(smem + ((a1 - sb) >> 2)) = p1;
            }
            __syncwarp();
        }

        uint32_t pa[8][4];
#pragma unroll
        for (int kg = 0; kg < 8; kg++) {
            uint32_t ad = sQ + w * 4096 + (l & 15) * 256 +
                          (((2 * kg + (l >> 4)) ^ lx) << 4);
            LDSM4(pa[kg][0], pa[kg][1], pa[kg][2], pa[kg][3], ad);
            CVT_TF32(pa[kg][0]); CVT_TF32(pa[kg][1]);
            CVT_TF32(pa[kg][2]); CVT_TF32(pa[kg][3]);
        }

        // ---- O += P V ----
#pragma unroll
        for (int s = 0; s < 8; s += 2) {
#pragma unroll
            for (int nf = 0; nf < 8; nf++) {
                uint32_t bv[4];
                uint32_t ad = sVb[buf] + (nf * 8 + lx) * 256 +
                              (((2 * s + ((l >> 3) & 3)) ^ lx) << 4);
                LDSM4(bv[0], bv[1], bv[2], bv[3], ad);
                MMA_TF32(oacc[nf], pa[s],     bv[0], bv[1]);
                MMA_TF32(oacc[nf], pa[s + 1], bv[2], bv[3]);
            }
        }

        __syncthreads();
        buf ^= 1;
    }
#undef STAGE_KV

    // ---- reduce sums across the 4 lanes sharing each row, write O ----
    {
#pragma unroll
        for (int o = 1; o < 4; o <<= 1) {
            sr0 += __shfl_xor_sync(0xffffffffu, sr0, o);
            sr1 += __shfl_xor_sync(0xffffffffu, sr1, o);
        }
        const float i0 = (sr0 > 0.f) ? 1.f / sr0 : 0.f;
        const float i1 = (sr1 > 0.f) ? 1.f / sr1 : 0.f;
        const int r0 = m0 + mw + (l >> 2);
#pragma unroll
        for (int nf = 0; nf < 8; nf++) {
            int col = h * DK + nf * 8 + (l & 3) * 2;
            float2 o0 = { rtf32(oacc[nf][0] * i0), rtf32(oacc[nf][1] * i0) };
            float2 o1 = { rtf32(oacc[nf][2] * i1), rtf32(oacc[nf][3] * i1) };
            *(float2*)&Ao[((size_t)(b * LQ + r0)) * DM + col]     = o0;
            *(float2*)&Ao[((size_t)(b * LQ + r0 + 8)) * DM + col] = o1;
        }
    }
}

// ---------------------------------------------------------------------------
extern "C" void kernel_launch(void* const* d_in, const int* in_sizes, int n_in,
                              void* d_out, int out_size)
{
    const float* q       = (const float*)d_in[0];
    const float* k       = (const float*)d_in[1];
    const float* v       = (const float*)d_in[2];
    const int*   b_idx   = (const int*)  d_in[3];
    const int*   mask    = (const int*)  d_in[4];
    const float* Wq      = (const float*)d_in[5];
    const float* bq      = (const float*)d_in[6];
    const float* Wk      = (const float*)d_in[7];
    const float* bk      = (const float*)d_in[8];
    const float* Wv      = (const float*)d_in[9];
    const float* bv      = (const float*)d_in[10];
    const float* Wo      = (const float*)d_in[11];
    const float* bo      = (const float*)d_in[12];
    const float* b_table = (const float*)d_in[13];
    float* out = (float*)d_out;

    void *Qp_, *Kp_, *Vt_, *Ao_, *bm_;
    cudaGetSymbolAddress(&Qp_, g_Qp);
    cudaGetSymbolAddress(&Kp_, g_Kp);
    cudaGetSymbolAddress(&Vt_, g_Vt);
    cudaGetSymbolAddress(&Ao_, g_Ao);
    cudaGetSymbolAddress(&bm_, g_bm);
    float* Qp = (float*)Qp_;
    float* Kp = (float*)Kp_;
    float* Vt = (float*)Vt_;
    float* Ao = (float*)Ao_;
    unsigned short* bm = (unsigned short*)bm_;

    static int attr_set = 0;
    if (!attr_set) {
        cudaFuncSetAttribute((const void*)gemm_bt_tf32<1,1,1,0>, cudaFuncAttributeMaxDynamicSharedMemorySize, 65536);
        cudaFuncSetAttribute((const void*)gemm_bt_tf32<1,1,1,1>, cudaFuncAttributeMaxDynamicSharedMemorySize, 69632);
        cudaFuncSetAttribute((const void*)gemm_bt_tf32<0,1,0,0>, cudaFuncAttributeMaxDynamicSharedMemorySize, 65536);
        cudaFuncSetAttribute((const void*)flash_attn_tf32,       cudaFuncAttributeMaxDynamicSharedMemorySize, 101904);
        attr_set = 1;
    }

    // pack bias/mask (h-invariant; L2-resident for flash)
    const int NB4 = BSZ * LQ * LK / 4;
    pack_bm_kernel<<<1024, 256>>>((const int4*)b_idx, (const int4*)mask, (ushort4*)bm, NB4);

    // projections (frags rounded in-loop; outputs rounded)
    gemm_bt_tf32<1,1,1,0><<<dim3(DM / 128, (BSZ * LQ) / 128), 128, 65536>>>(q, Wq, bq, Qp, BSZ * LQ, DM, DM);
    gemm_bt_tf32<1,1,1,0><<<dim3(DM / 128, (BSZ * LK) / 128), 128, 65536>>>(k, Wk, bk, Kp, BSZ * LK, DM, DM);
    gemm_bt_tf32<1,1,1,1><<<dim3(DM / 128, (BSZ * LK) / 128), 128, 69632>>>(v, Wv, bv, Vt, BSZ * LK, DM, DM);

    // fused attention (h fastest for packed bm L2 reuse)
    flash_attn_tf32<<<dim3(NH, LQ / 64, BSZ), 128, 101904>>>(
        Qp, Kp, Vt, bm, b_table, Ao);

    // output projection (A pre-rounded at flash epilogue; output fp32)
    gemm_bt_tf32<0,1,0,0><<<dim3(DM / 128, (BSZ * LQ) / 128), 128, 65536>>>(Ao, Wo, bo, out, BSZ * LQ, DM, DM);
}

// round 14
// speedup vs baseline: 1.2355x; 1.0071x over previous
#include <cuda_runtime.h>
#include <cstdint>

#define BSZ 4
#define LQ  512
#define LK  2048
#define DM  1024
#define NH  16
#define DK  64
#define VOCAB_B 900

// ---------------- scratch (static device memory; no runtime alloc) ----------
__device__ float g_Qp[BSZ * LQ * DM];
__device__ float g_Kp[BSZ * LK * DM];
__device__ float g_Vt[BSZ * DM * LK];                  // V projected+transposed
__device__ float g_Ao[BSZ * LQ * DM];
__device__ float g_Wr[4 * DM * DM];                    // tf32-rounded weights
__device__ unsigned short g_bm[BSZ * LQ * LK];         // packed b_idx|mask<<15

// ---------------- PTX helpers ----------------------------------------------
__device__ __forceinline__ uint32_t s_u32(const void* p) {
    uint32_t a;
    asm("{.reg .u64 t; cvta.to.shared.u64 t, %1; cvt.u32.u64 %0, t;}"
        : "=r"(a) : "l"(p));
    return a;
}

__device__ __forceinline__ float rtf32(float x) {
    uint32_t u = __float_as_uint(x);
    asm("cvt.rna.tf32.f32 %0,%0;" : "+r"(u));
    return __uint_as_float(u);
}

#define LDSM4(R0,R1,R2,R3,ADDR) \
    asm volatile("ldmatrix.sync.aligned.m8n8.x4.shared.b16 {%0,%1,%2,%3},[%4];" \
        : "=r"(R0),"=r"(R1),"=r"(R2),"=r"(R3) : "r"(ADDR))

#define CVT_TF32(T) asm volatile("cvt.rna.tf32.f32 %0,%0;" : "+r"(T))

#define MMA_TF32(D,A,B0,B1) \
    asm volatile("mma.sync.aligned.m16n8k8.row.col.f32.tf32.tf32.f32 " \
        "{%0,%1,%2,%3},{%4,%5,%6,%7},{%8,%9},{%0,%1,%2,%3};" \
        : "+f"(D[0]),"+f"(D[1]),"+f"(D[2]),"+f"(D[3]) \
        : "r"(A[0]),"r"(A[1]),"r"(A[2]),"r"(A[3]),"r"(B0),"r"(B1))

#define CP16(DST,SRC) \
    asm volatile("cp.async.cg.shared.global [%0],[%1],16;" :: "r"(DST),"l"(SRC))
#define CPCOMMIT  asm volatile("cp.async.commit_group;")
#define CPWAIT0   asm volatile("cp.async.wait_group 0;")
#define CPWAIT1   asm volatile("cp.async.wait_group 1;")

// ============================================================================
// tf32 rounding pass (weights only): grid-strided float4
// ============================================================================
__global__ __launch_bounds__(256) void round_tf32_kernel(
    const float4* __restrict__ in, float4* __restrict__ out, int n4)
{
    const int s = gridDim.x * 256;
    for (int i = blockIdx.x * 256 + threadIdx.x; i < n4; i += s) {
        float4 v = in[i];
        v.x = rtf32(v.x); v.y = rtf32(v.y);
        v.z = rtf32(v.z); v.w = rtf32(v.w);
        out[i] = v;
    }
}

// ============================================================================
// pack b_idx + mask -> uint16 (idx | mask<<15), 4x ILP grid-strided
// ============================================================================
__device__ __forceinline__ ushort4 pack4(int4 ix, int4 mk) {
    ushort4 o;
    o.x = (unsigned short)(ix.x | (mk.x << 15));
    o.y = (unsigned short)(ix.y | (mk.y << 15));
    o.z = (unsigned short)(ix.z | (mk.z << 15));
    o.w = (unsigned short)(ix.w | (mk.w << 15));
    return o;
}
__global__ __launch_bounds__(256) void pack_bm_kernel(
    const int4* __restrict__ b_idx, const int4* __restrict__ mask,
    ushort4* __restrict__ bm, int n4)
{
    const int s = gridDim.x * 256;
    int i = blockIdx.x * 256 + threadIdx.x;
    if (i + 3 * s < n4) {
        int4 a0 = b_idx[i],         a1 = b_idx[i + s],
             a2 = b_idx[i + 2 * s], a3 = b_idx[i + 3 * s];
        int4 m0 = mask[i],          m1 = mask[i + s],
             m2 = mask[i + 2 * s],  m3 = mask[i + 3 * s];
        bm[i]         = pack4(a0, m0);
        bm[i + s]     = pack4(a1, m1);
        bm[i + 2 * s] = pack4(a2, m2);
        bm[i + 3 * s] = pack4(a3, m3);
    } else {
        for (; i < n4; i += s) bm[i] = pack4(b_idx[i], mask[i]);
    }
}

// ============================================================================
// tf32 GEMM: C = A @ B^T + bias. CTA 128x128, 4 warps, warp 64x64,
// BK=32, 2-deep cp.async pipeline, 2 CTAs/SM. B PRE-ROUNDED (no CVTB).
// CVTA: round A frags in-loop. RND: round outputs.
// TRANSV: write transposed to Vt[b][n][m%LK] via smem.
// ============================================================================
template<int CVTA, int RND, int TRANSV>
__global__ __launch_bounds__(128, 2) void gemm_bt_tf32(
    const float* __restrict__ A, const float* __restrict__ B,
    const float* __restrict__ bias, float* __restrict__ C,
    int M, int N, int K)
{
    extern __shared__ float smem[];
    const uint32_t sbase = s_u32(smem);
    const int tid = threadIdx.x;
    const int m0 = blockIdx.y * 128, n0 = blockIdx.x * 128;
    const int l  = tid & 31, w = tid >> 5;
    const int mw = (w >> 1) * 64, nw = (w & 1) * 64;
    const int lrow = l & 15, lq = l >> 4, lx = l & 7;

    float acc[4][8][4];
#pragma unroll
    for (int i = 0; i < 4; i++)
#pragma unroll
        for (int j = 0; j < 8; j++)
#pragma unroll
            for (int r = 0; r < 4; r++) acc[i][j][r] = 0.f;

    const int NIT = K >> 5;

#define STAGE_G(IT, BUF) do {                                                  \
    uint32_t sA_ = sbase + (BUF) * 32768;                                      \
    uint32_t sB_ = sA_ + 16384;                                                \
    const float* Ag_ = A + (size_t)(m0) * K + (IT) * 32;                       \
    const float* Bg_ = B + (size_t)(n0) * K + (IT) * 32;                       \
    _Pragma("unroll")                                                          \
    for (int i_ = 0; i_ < 8; i_++) {                                           \
        int gi_ = tid + i_ * 128;                                              \
        int r_ = gi_ >> 3, g_ = gi_ & 7;                                       \
        CP16(sA_ + r_ * 128 + (((g_ ^ (r_ & 7)) << 4)),                        \
             Ag_ + (size_t)r_ * K + g_ * 4);                                   \
    }                                                                          \
    _Pragma("unroll")                                                          \
    for (int i_ = 0; i_ < 8; i_++) {                                           \
        int gi_ = tid + i_ * 128;                                              \
        int r_ = gi_ >> 3, g_ = gi_ & 7;                                       \
        CP16(sB_ + r_ * 128 + (((g_ ^ (r_ & 7)) << 4)),                        \
             Bg_ + (size_t)r_ * K + g_ * 4);                                   \
    }                                                                          \
} while (0)

    STAGE_G(0, 0);
    CPCOMMIT;

    int buf = 0;
    for (int it = 0; it < NIT; ++it) {
        if (it + 1 < NIT) { STAGE_G(it + 1, buf ^ 1); CPCOMMIT; CPWAIT1; }
        else              { CPWAIT0; }
        __syncthreads();

        const uint32_t sA = sbase + buf * 32768;
        const uint32_t sB = sA + 16384;
        const uint32_t aAdr0 = sA + (mw + lrow) * 128;
        const uint32_t bAdr0 = sB + (nw + (l & 7)) * 128;

#pragma unroll
        for (int s = 0; s < 4; s += 2) {
            uint32_t bfr[8][4];
#pragma unroll
            for (int nf = 0; nf < 8; nf++) {
                uint32_t ad = bAdr0 + nf * 1024 +
                              (((2 * s + ((l >> 3) & 3)) ^ lx) << 4);
                LDSM4(bfr[nf][0], bfr[nf][1], bfr[nf][2], bfr[nf][3], ad);
            }
#pragma unroll
            for (int ss = 0; ss < 2; ss++) {
                uint32_t a[4][4];
#pragma unroll
                for (int mf = 0; mf < 4; mf++) {
                    uint32_t ad = aAdr0 + mf * 2048 +
                                  (((2 * (s + ss) + lq) ^ lx) << 4);
                    LDSM4(a[mf][0], a[mf][1], a[mf][2], a[mf][3], ad);
                    if (CVTA) {
                        CVT_TF32(a[mf][0]); CVT_TF32(a[mf][1]);
                        CVT_TF32(a[mf][2]); CVT_TF32(a[mf][3]);
                    }
                }
#pragma unroll
                for (int mf = 0; mf < 4; mf++)
#pragma unroll
                    for (int nf = 0; nf < 8; nf++)
                        MMA_TF32(acc[mf][nf], a[mf], bfr[nf][2 * ss], bfr[nf][2 * ss + 1]);
            }
        }
        __syncthreads();
        buf ^= 1;
    }
#undef STAGE_G

    if (TRANSV) {
        // stage rounded acc+bias as [n][m] (pitch 132), write Vt coalesced
        __syncthreads();
#pragma unroll
        for (int mf = 0; mf < 4; mf++) {
            int mloc = mw + mf * 16 + (l >> 2);
#pragma unroll
            for (int nf = 0; nf < 8; nf++) {
                int nloc = nw + nf * 8 + (l & 3) * 2;
                float2 bb = *(const float2*)&bias[n0 + nloc];
                smem[(nloc)     * 132 + mloc]     = rtf32(acc[mf][nf][0] + bb.x);
                smem[(nloc + 1) * 132 + mloc]     = rtf32(acc[mf][nf][1] + bb.y);
                smem[(nloc)     * 132 + mloc + 8] = rtf32(acc[mf][nf][2] + bb.x);
                smem[(nloc + 1) * 132 + mloc + 8] = rtf32(acc[mf][nf][3] + bb.y);
            }
        }
        __syncthreads();
        const int bb_ = m0 / LK;
        const int kb_ = m0 % LK;
#pragma unroll
        for (int i = 0; i < 32; i++) {
            int n = w * 32 + i;
            float4 vv = *(const float4*)&smem[n * 132 + 4 * l];
            *(float4*)&C[((size_t)(bb_ * DM + n0 + n)) * LK + kb_ + 4 * l] = vv;
        }
    } else {
#pragma unroll
        for (int mf = 0; mf < 4; mf++) {
            int row = m0 + mw + mf * 16 + (l >> 2);
#pragma unroll
            for (int nf = 0; nf < 8; nf++) {
                int col = n0 + nw + nf * 8 + (l & 3) * 2;
                float2 bb = *(const float2*)&bias[col];
                float2 o0, o1;
                o0.x = acc[mf][nf][0] + bb.x; o0.y = acc[mf][nf][1] + bb.y;
                o1.x = acc[mf][nf][2] + bb.x; o1.y = acc[mf][nf][3] + bb.y;
                if (RND) {
                    o0.x = rtf32(o0.x); o0.y = rtf32(o0.y);
                    o1.x = rtf32(o1.x); o1.y = rtf32(o1.y);
                }
                *(float2*)&C[(size_t)row * N + col]       = o0;
                *(float2*)&C[(size_t)(row + 8) * N + col] = o1;
            }
        }
    }
}

// ============================================================================
// Fused flash attention. CTA: 64 queries, 4 warps, 2 CTAs/SM.
// No-max softmax, branchless (mask selects exp ARGUMENT; exp unconditional).
// ============================================================================
__global__ __launch_bounds__(128, 2) void flash_attn_tf32(
    const float* __restrict__ Qp, const float* __restrict__ Kp,
    const float* __restrict__ Vt, const unsigned short* __restrict__ bm,
    const float* __restrict__ b_table, float* __restrict__ Ao)
{
    extern __shared__ float smem[];
    const uint32_t sb = s_u32(smem);
    const uint32_t sQ = sb;                       // aliased by P after Q consumed
    const uint32_t sKb[2]  = { sb + 16384, sb + 57344 };
    const uint32_t sVb[2]  = { sb + 32768, sb + 73728 };
    const uint32_t sBMb[2] = { sb + 49152, sb + 90112 };
    const uint32_t bmOff[2] = { 49152, 90112 };
    float* btm = smem + 98304 / 4;

    const int tid = threadIdx.x;
    const int h = blockIdx.x, b = blockIdx.z;
    const int m0 = blockIdx.y * 64;
    const int l = tid & 31, w = tid >> 5;
    const int mw = w * 16;
    const int lx = l & 7;

    for (int i = tid; i < VOCAB_B; i += 128) btm[i] = b_table[i * NH + h];

    const float* Qg = Qp + ((size_t)(b * LQ + m0)) * DM + h * DK;
    const float* Kg = Kp + ((size_t)(b * LK)) * DM + h * DK;
    const float* Vg = Vt + ((size_t)(b * DM + h * DK)) * LK;
    const unsigned short* BMg = bm + ((size_t)(b * LQ + m0)) * LK;

#pragma unroll
    for (int i = 0; i < 8; i++) {
        int gi = tid + i * 128;
        int r = gi >> 4, g = gi & 15;
        CP16(sQ + r * 256 + (((g ^ (r & 7)) << 4)), Qg + (size_t)r * DM + g * 4);
    }

#define STAGE_KV(IT, BUF) do {                                                 \
    const float* Ksrc_ = Kg + (size_t)((IT) * 64) * DM;                        \
    const float* Vsrc_ = Vg + (IT) * 64;                                       \
    const unsigned short* Bsrc_ = BMg + (IT) * 64;                             \
    _Pragma("unroll")                                                          \
    for (int i_ = 0; i_ < 8; i_++) {                                           \
        int gi_ = tid + i_ * 128;                                              \
        int r_ = gi_ >> 4, g_ = gi_ & 15;                                      \
        CP16(sKb[BUF] + r_ * 256 + (((g_ ^ (r_ & 7)) << 4)),                   \
             Ksrc_ + (size_t)r_ * DM + g_ * 4);                                \
    }                                                                          \
    _Pragma("unroll")                                                          \
    for (int i_ = 0; i_ < 8; i_++) {                                           \
        int gi_ = tid + i_ * 128;                                              \
        int r_ = gi_ >> 4, g_ = gi_ & 15;                                      \
        CP16(sVb[BUF] + r_ * 256 + (((g_ ^ (r_ & 7)) << 4)),                   \
             Vsrc_ + (size_t)r_ * LK + g_ * 4);                                \
    }                                                                          \
    _Pragma("unroll")                                                          \
    for (int i_ = 0; i_ < 4; i_++) {                                           \
        int gi_ = tid + i_ * 128;                                              \
        int r_ = gi_ >> 3, g_ = gi_ & 7;                                       \
        CP16(sBMb[BUF] + r_ * 128 + (((g_ ^ (r_ & 7)) << 4)),                  \
             Bsrc_ + (size_t)r_ * LK + g_ * 8);                                \
    }                                                                          \
} while (0)

    STAGE_KV(0, 0);
    CPCOMMIT;

    uint32_t aq[8][4];
    float oacc[8][4];
#pragma unroll
    for (int nf = 0; nf < 8; nf++)
#pragma unroll
        for (int r = 0; r < 4; r++) oacc[nf][r] = 0.f;
    float sr0 = 0.f, sr1 = 0.f;          // per-lane partial sums

    const int lr = mw + (l >> 2);
    const uint32_t lrx = (uint32_t)(lr & 7);

    int buf = 0;
    for (int it = 0; it < LK / 64; ++it) {
        if (it + 1 < LK / 64) { STAGE_KV(it + 1, buf ^ 1); CPCOMMIT; CPWAIT1; }
        else                  { CPWAIT0; }
        __syncthreads();

        if (it == 0) {
#pragma unroll
            for (int kg = 0; kg < 8; kg++) {
                uint32_t ad = sQ + (mw + (l & 15)) * 256 +
                              (((2 * kg + (l >> 4)) ^ lx) << 4);
                LDSM4(aq[kg][0], aq[kg][1], aq[kg][2], aq[kg][3], ad);
            }
        }

        // ---- S = Q K^T ----
        float sval[8][4];
#pragma unroll
        for (int nf = 0; nf < 8; nf++)
#pragma unroll
            for (int r = 0; r < 4; r++) sval[nf][r] = 0.f;

#pragma unroll
        for (int s = 0; s < 8; s += 2) {
#pragma unroll
            for (int nf = 0; nf < 8; nf++) {
                uint32_t kb[4];
                uint32_t ad = sKb[buf] + (nf * 8 + lx) * 256 +
                              (((2 * s + ((l >> 3) & 3)) ^ lx) << 4);
                LDSM4(kb[0], kb[1], kb[2], kb[3], ad);
                MMA_TF32(sval[nf], aq[s],     kb[0], kb[1]);
                MMA_TF32(sval[nf], aq[s + 1], kb[2], kb[3]);
            }
        }

        // ---- scale + bias gather + mask (SELECT) then unconditional exp ----
        {
            const uint32_t base = bmOff[buf] / 4 + lr * 32 + (l & 3);
            const uint32_t* sm32 = (const uint32_t*)smem;
#pragma unroll
            for (int nf = 0; nf < 8; nf++) {
                uint32_t o = base + (((uint32_t)nf ^ lrx) << 2);
                uint32_t e01 = sm32[o];
                uint32_t e23 = sm32[o + 8 * 32];
                uint32_t e0 = e01 & 0xffffu, e1 = e01 >> 16;
                uint32_t e2 = e23 & 0xffffu, e3 = e23 >> 16;
                float a0 = (e0 & 0x8000u) ? sval[nf][0] * 0.125f + btm[e0 & 0x3ffu] : -1e30f;
                float a1 = (e1 & 0x8000u) ? sval[nf][1] * 0.125f + btm[e1 & 0x3ffu] : -1e30f;
                float a2 = (e2 & 0x8000u) ? sval[nf][2] * 0.125f + btm[e2 & 0x3ffu] : -1e30f;
                float a3 = (e3 & 0x8000u) ? sval[nf][3] * 0.125f + btm[e3 & 0x3ffu] : -1e30f;
                sval[nf][0] = __expf(a0);
                sval[nf][1] = __expf(a1);
                sval[nf][2] = __expf(a2);
                sval[nf][3] = __expf(a3);
                sr0 += sval[nf][0] + sval[nf][1];
                sr1 += sval[nf][2] + sval[nf][3];
            }
        }

        // ---- P -> per-warp patch (aliases this warp's Q rows) ----
        {
            const uint32_t pb = sQ + w * 4096;
            const int rs0 = l >> 2;
            const uint32_t boff = ((l & 1) << 3);
            __syncwarp();
#pragma unroll
            for (int nf = 0; nf < 8; nf++) {
                int g = nf * 2 + ((l & 3) >> 1);
                uint32_t a0 = pb + rs0 * 256 + (((g ^ rs0) << 4)) + boff;
                uint32_t a1 = pb + (rs0 + 8) * 256 + (((g ^ rs0) << 4)) + boff;
                float2 p0 = { sval[nf][0], sval[nf][1] };
                float2 p1 = { sval[nf][2], sval[nf][3] };
                *(float2*)(smem + ((a0 - sb) >> 2)) = p0;
                *(float2*)(smem + ((a1 - sb) >> 2)) = p1;
            }
            __syncwarp();
        }

        uint32_t pa[8][4];
#pragma unroll
        for (int kg = 0; kg < 8; kg++) {
            uint32_t ad = sQ + w * 4096 + (l & 15) * 256 +
                          (((2 * kg + (l >> 4)) ^ lx) << 4);
            LDSM4(pa[kg][0], pa[kg][1], pa[kg][2], pa[kg][3], ad);
            CVT_TF32(pa[kg][0]); CVT_TF32(pa[kg][1]);
            CVT_TF32(pa[kg][2]); CVT_TF32(pa[kg][3]);
        }

        // ---- O += P V ----
#pragma unroll
        for (int s = 0; s < 8; s += 2) {
#pragma unroll
            for (int nf = 0; nf < 8; nf++) {
                uint32_t bv[4];
                uint32_t ad = sVb[buf] + (nf * 8 + lx) * 256 +
                              (((2 * s + ((l >> 3) & 3)) ^ lx) << 4);
                LDSM4(bv[0], bv[1], bv[2], bv[3], ad);
                MMA_TF32(oacc[nf], pa[s],     bv[0], bv[1]);
                MMA_TF32(oacc[nf], pa[s + 1], bv[2], bv[3]);
            }
        }

        __syncthreads();
        buf ^= 1;
    }
#undef STAGE_KV

    // ---- reduce sums across the 4 lanes sharing each row, write O ----
    {
#pragma unroll
        for (int o = 1; o < 4; o <<= 1) {
            sr0 += __shfl_xor_sync(0xffffffffu, sr0, o);
            sr1 += __shfl_xor_sync(0xffffffffu, sr1, o);
        }
        const float i0 = (sr0 > 0.f) ? 1.f / sr0 : 0.f;
        const float i1 = (sr1 > 0.f) ? 1.f / sr1 : 0.f;
        const int r0 = m0 + mw + (l >> 2);
#pragma unroll
        for (int nf = 0; nf < 8; nf++) {
            int col = h * DK + nf * 8 + (l & 3) * 2;
            float2 o0 = { rtf32(oacc[nf][0] * i0), rtf32(oacc[nf][1] * i0) };
            float2 o1 = { rtf32(oacc[nf][2] * i1), rtf32(oacc[nf][3] * i1) };
            *(float2*)&Ao[((size_t)(b * LQ + r0)) * DM + col]     = o0;
            *(float2*)&Ao[((size_t)(b * LQ + r0 + 8)) * DM + col] = o1;
        }
    }
}

// ---------------------------------------------------------------------------
extern "C" void kernel_launch(void* const* d_in, const int* in_sizes, int n_in,
                              void* d_out, int out_size)
{
    const float* q       = (const float*)d_in[0];
    const float* k       = (const float*)d_in[1];
    const float* v       = (const float*)d_in[2];
    const int*   b_idx   = (const int*)  d_in[3];
    const int*   mask    = (const int*)  d_in[4];
    const float* Wq      = (const float*)d_in[5];
    const float* bq      = (const float*)d_in[6];
    const float* Wk      = (const float*)d_in[7];
    const float* bk      = (const float*)d_in[8];
    const float* Wv      = (const float*)d_in[9];
    const float* bv      = (const float*)d_in[10];
    const float* Wo      = (const float*)d_in[11];
    const float* bo      = (const float*)d_in[12];
    const float* b_table = (const float*)d_in[13];
    float* out = (float*)d_out;

    void *Qp_, *Kp_, *Vt_, *Ao_, *bm_, *Wr_;
    cudaGetSymbolAddress(&Qp_, g_Qp);
    cudaGetSymbolAddress(&Kp_, g_Kp);
    cudaGetSymbolAddress(&Vt_, g_Vt);
    cudaGetSymbolAddress(&Ao_, g_Ao);
    cudaGetSymbolAddress(&bm_, g_bm);
    cudaGetSymbolAddress(&Wr_, g_Wr);
    float* Qp = (float*)Qp_;
    float* Kp = (float*)Kp_;
    float* Vt = (float*)Vt_;
    float* Ao = (float*)Ao_;
    float* Wr = (float*)Wr_;
    unsigned short* bm = (unsigned short*)bm_;

    static int attr_set = 0;
    if (!attr_set) {
        cudaFuncSetAttribute((const void*)gemm_bt_tf32<1,1,0>, cudaFuncAttributeMaxDynamicSharedMemorySize, 65536);
        cudaFuncSetAttribute((const void*)gemm_bt_tf32<1,1,1>, cudaFuncAttributeMaxDynamicSharedMemorySize, 69632);
        cudaFuncSetAttribute((const void*)gemm_bt_tf32<0,0,0>, cudaFuncAttributeMaxDynamicSharedMemorySize, 65536);
        cudaFuncSetAttribute((const void*)flash_attn_tf32,     cudaFuncAttributeMaxDynamicSharedMemorySize, 101904);
        attr_set = 1;
    }

    // precompute: pack bias/mask + round weights (8 MB total traffic)
    const int NB4 = BSZ * LQ * LK / 4;
    const int NW4 = DM * DM / 4;
    pack_bm_kernel<<<1024, 256>>>((const int4*)b_idx, (const int4*)mask, (ushort4*)bm, NB4);
    round_tf32_kernel<<<256, 256>>>((const float4*)Wq, (float4*)(Wr + 0 * DM * DM), NW4);
    round_tf32_kernel<<<256, 256>>>((const float4*)Wk, (float4*)(Wr + 1 * DM * DM), NW4);
    round_tf32_kernel<<<256, 256>>>((const float4*)Wv, (float4*)(Wr + 2 * DM * DM), NW4);
    round_tf32_kernel<<<256, 256>>>((const float4*)Wo, (float4*)(Wr + 3 * DM * DM), NW4);

    // projections (A rounded in-loop; B pre-rounded; outputs rounded)
    gemm_bt_tf32<1,1,0><<<dim3(DM / 128, (BSZ * LQ) / 128), 128, 65536>>>(q, Wr + 0 * DM * DM, bq, Qp, BSZ * LQ, DM, DM);
    gemm_bt_tf32<1,1,0><<<dim3(DM / 128, (BSZ * LK) / 128), 128, 65536>>>(k, Wr + 1 * DM * DM, bk, Kp, BSZ * LK, DM, DM);
    gemm_bt_tf32<1,1,1><<<dim3(DM / 128, (BSZ * LK) / 128), 128, 69632>>>(v, Wr + 2 * DM * DM, bv, Vt, BSZ * LK, DM, DM);

    // fused attention (h fastest for packed bm L2 reuse)
    flash_attn_tf32<<<dim3(NH, LQ / 64, BSZ), 128, 101904>>>(
        Qp, Kp, Vt, bm, b_table, Ao);

    // output projection (A pre-rounded at flash epilogue; output fp32)
    gemm_bt_tf32<0,0,0><<<dim3(DM / 128, (BSZ * LQ) / 128), 128, 65536>>>(Ao, Wr + 3 * DM * DM, bo, out, BSZ * LQ, DM, DM);
}

// round 15
// speedup vs baseline: 1.3686x; 1.1077x over previous
#include <cuda_runtime.h>
#include <cstdint>

#define BSZ 4
#define LQ  512
#define LK  2048
#define DM  1024
#define NH  16
#define DK  64
#define VOCAB_B 900

// ---------------- scratch (static device memory; no runtime alloc) ----------
__device__ float g_Qp[BSZ * LQ * DM];
__device__ float g_Kp[BSZ * LK * DM];
__device__ float g_Vt[BSZ * DM * LK];                  // V projected+transposed
__device__ float g_Ao[BSZ * LQ * DM];
__device__ float g_Wr[4 * DM * DM];                    // tf32-rounded weights
__device__ unsigned short g_bm[BSZ * LQ * LK];         // packed b_idx|mask<<15

// ---------------- PTX helpers ----------------------------------------------
__device__ __forceinline__ uint32_t s_u32(const void* p) {
    uint32_t a;
    asm("{.reg .u64 t; cvta.to.shared.u64 t, %1; cvt.u32.u64 %0, t;}"
        : "=r"(a) : "l"(p));
    return a;
}

__device__ __forceinline__ float rtf32(float x) {
    uint32_t u = __float_as_uint(x);
    asm("cvt.rna.tf32.f32 %0,%0;" : "+r"(u));
    return __uint_as_float(u);
}

#define LDSM4(R0,R1,R2,R3,ADDR) \
    asm volatile("ldmatrix.sync.aligned.m8n8.x4.shared.b16 {%0,%1,%2,%3},[%4];" \
        : "=r"(R0),"=r"(R1),"=r"(R2),"=r"(R3) : "r"(ADDR))

#define CVT_TF32(T) asm volatile("cvt.rna.tf32.f32 %0,%0;" : "+r"(T))

#define MMA_TF32(D,A,B0,B1) \
    asm volatile("mma.sync.aligned.m16n8k8.row.col.f32.tf32.tf32.f32 " \
        "{%0,%1,%2,%3},{%4,%5,%6,%7},{%8,%9},{%0,%1,%2,%3};" \
        : "+f"(D[0]),"+f"(D[1]),"+f"(D[2]),"+f"(D[3]) \
        : "r"(A[0]),"r"(A[1]),"r"(A[2]),"r"(A[3]),"r"(B0),"r"(B1))

#define CP16(DST,SRC) \
    asm volatile("cp.async.cg.shared.global [%0],[%1],16;" :: "r"(DST),"l"(SRC))
#define CPCOMMIT  asm volatile("cp.async.commit_group;")
#define CPWAIT0   asm volatile("cp.async.wait_group 0;")
#define CPWAIT1   asm volatile("cp.async.wait_group 1;")

// ============================================================================
// round all 4 weight matrices in ONE launch (blockIdx.y selects matrix)
// ============================================================================
__global__ __launch_bounds__(256) void round_w4_kernel(
    const float4* __restrict__ w0, const float4* __restrict__ w1,
    const float4* __restrict__ w2, const float4* __restrict__ w3,
    float4* __restrict__ out, int n4)
{
    const float4* src = (blockIdx.y == 0) ? w0 : (blockIdx.y == 1) ? w1 :
                        (blockIdx.y == 2) ? w2 : w3;
    float4* dst = out + (size_t)blockIdx.y * n4;
    const int s = gridDim.x * 256;
    for (int i = blockIdx.x * 256 + threadIdx.x; i < n4; i += s) {
        float4 v = src[i];
        v.x = rtf32(v.x); v.y = rtf32(v.y);
        v.z = rtf32(v.z); v.w = rtf32(v.w);
        dst[i] = v;
    }
}

// ============================================================================
// pack b_idx + mask -> uint16 (idx | mask<<15), 4x ILP grid-strided
// ============================================================================
__device__ __forceinline__ ushort4 pack4(int4 ix, int4 mk) {
    ushort4 o;
    o.x = (unsigned short)(ix.x | (mk.x << 15));
    o.y = (unsigned short)(ix.y | (mk.y << 15));
    o.z = (unsigned short)(ix.z | (mk.z << 15));
    o.w = (unsigned short)(ix.w | (mk.w << 15));
    return o;
}
__global__ __launch_bounds__(256) void pack_bm_kernel(
    const int4* __restrict__ b_idx, const int4* __restrict__ mask,
    ushort4* __restrict__ bm, int n4)
{
    const int s = gridDim.x * 256;
    int i = blockIdx.x * 256 + threadIdx.x;
    if (i + 3 * s < n4) {
        int4 a0 = b_idx[i],         a1 = b_idx[i + s],
             a2 = b_idx[i + 2 * s], a3 = b_idx[i + 3 * s];
        int4 m0 = mask[i],          m1 = mask[i + s],
             m2 = mask[i + 2 * s],  m3 = mask[i + 3 * s];
        bm[i]         = pack4(a0, m0);
        bm[i + s]     = pack4(a1, m1);
        bm[i + 2 * s] = pack4(a2, m2);
        bm[i + 3 * s] = pack4(a3, m3);
    } else {
        for (; i < n4; i += s) bm[i] = pack4(b_idx[i], mask[i]);
    }
}

// ============================================================================
// FUSED Q/K/V projection: one launch, blockIdx.y in [0,144) selects
//   [0,16)   Q proj -> Qp (rounded)
//   [16,80)  K proj -> Kp (rounded)
//   [80,144) V proj -> Vt (transposed, rounded)
// CTA 128x128, 4 warps, warp 64x64, BK=32, 2-deep pipeline, 2 CTAs/SM.
// A frags rounded in-loop; B (weights) pre-rounded.
// ============================================================================
__global__ __launch_bounds__(128, 2) void proj_qkv_tf32(
    const float* __restrict__ q, const float* __restrict__ k,
    const float* __restrict__ v, const float* __restrict__ Wr,
    const float* __restrict__ bq, const float* __restrict__ bk,
    const float* __restrict__ bv,
    float* __restrict__ Qp, float* __restrict__ Kp, float* __restrict__ Vt)
{
    extern __shared__ float smem[];
    const uint32_t sbase = s_u32(smem);
    const int tid = threadIdx.x;
    const int y = blockIdx.y;

    const float* A;  const float* B;  const float* bias;  float* C;
    int m0;  bool transv;
    if (y < 16)      { A = q; B = Wr;              bias = bq; C = Qp; m0 = y * 128;        transv = false; }
    else if (y < 80) { A = k; B = Wr + DM * DM;    bias = bk; C = Kp; m0 = (y - 16) * 128; transv = false; }
    else             { A = v; B = Wr + 2 * DM * DM; bias = bv; C = Vt; m0 = (y - 80) * 128; transv = true; }

    const int n0 = blockIdx.x * 128;
    const int l  = tid & 31, w = tid >> 5;
    const int mw = (w >> 1) * 64, nw = (w & 1) * 64;
    const int lrow = l & 15, lq_ = l >> 4, lx = l & 7;

    float acc[4][8][4];
#pragma unroll
    for (int i = 0; i < 4; i++)
#pragma unroll
        for (int j = 0; j < 8; j++)
#pragma unroll
            for (int r = 0; r < 4; r++) acc[i][j][r] = 0.f;

#define STAGE_P(IT, BUF) do {                                                  \
    uint32_t sA_ = sbase + (BUF) * 32768;                                      \
    uint32_t sB_ = sA_ + 16384;                                                \
    const float* Ag_ = A + (size_t)(m0) * DM + (IT) * 32;                      \
    const float* Bg_ = B + (size_t)(n0) * DM + (IT) * 32;                      \
    _Pragma("unroll")                                                          \
    for (int i_ = 0; i_ < 8; i_++) {                                           \
        int gi_ = tid + i_ * 128;                                              \
        int r_ = gi_ >> 3, g_ = gi_ & 7;                                       \
        CP16(sA_ + r_ * 128 + (((g_ ^ (r_ & 7)) << 4)),                        \
             Ag_ + (size_t)r_ * DM + g_ * 4);                                  \
    }                                                                          \
    _Pragma("unroll")                                                          \
    for (int i_ = 0; i_ < 8; i_++) {                                           \
        int gi_ = tid + i_ * 128;                                              \
        int r_ = gi_ >> 3, g_ = gi_ & 7;                                       \
        CP16(sB_ + r_ * 128 + (((g_ ^ (r_ & 7)) << 4)),                        \
             Bg_ + (size_t)r_ * DM + g_ * 4);                                  \
    }                                                                          \
} while (0)

    STAGE_P(0, 0);
    CPCOMMIT;

    int buf = 0;
    for (int it = 0; it < DM / 32; ++it) {
        if (it + 1 < DM / 32) { STAGE_P(it + 1, buf ^ 1); CPCOMMIT; CPWAIT1; }
        else                  { CPWAIT0; }
        __syncthreads();

        const uint32_t sA = sbase + buf * 32768;
        const uint32_t sB = sA + 16384;
        const uint32_t aAdr0 = sA + (mw + lrow) * 128;
        const uint32_t bAdr0 = sB + (nw + (l & 7)) * 128;

#pragma unroll
        for (int s = 0; s < 4; s += 2) {
            uint32_t bfr[8][4];
#pragma unroll
            for (int nf = 0; nf < 8; nf++) {
                uint32_t ad = bAdr0 + nf * 1024 +
                              (((2 * s + ((l >> 3) & 3)) ^ lx) << 4);
                LDSM4(bfr[nf][0], bfr[nf][1], bfr[nf][2], bfr[nf][3], ad);
            }
#pragma unroll
            for (int ss = 0; ss < 2; ss++) {
                uint32_t a[4][4];
#pragma unroll
                for (int mf = 0; mf < 4; mf++) {
                    uint32_t ad = aAdr0 + mf * 2048 +
                                  (((2 * (s + ss) + lq_) ^ lx) << 4);
                    LDSM4(a[mf][0], a[mf][1], a[mf][2], a[mf][3], ad);
                    CVT_TF32(a[mf][0]); CVT_TF32(a[mf][1]);
                    CVT_TF32(a[mf][2]); CVT_TF32(a[mf][3]);
                }
#pragma unroll
                for (int mf = 0; mf < 4; mf++)
#pragma unroll
                    for (int nf = 0; nf < 8; nf++)
                        MMA_TF32(acc[mf][nf], a[mf], bfr[nf][2 * ss], bfr[nf][2 * ss + 1]);
            }
        }
        __syncthreads();
        buf ^= 1;
    }
#undef STAGE_P

    if (transv) {
        // stage rounded acc+bias as [n][m] (pitch 132), write Vt coalesced
        __syncthreads();
#pragma unroll
        for (int mf = 0; mf < 4; mf++) {
            int mloc = mw + mf * 16 + (l >> 2);
#pragma unroll
            for (int nf = 0; nf < 8; nf++) {
                int nloc = nw + nf * 8 + (l & 3) * 2;
                float2 bb = *(const float2*)&bias[n0 + nloc];
                smem[(nloc)     * 132 + mloc]     = rtf32(acc[mf][nf][0] + bb.x);
                smem[(nloc + 1) * 132 + mloc]     = rtf32(acc[mf][nf][1] + bb.y);
                smem[(nloc)     * 132 + mloc + 8] = rtf32(acc[mf][nf][2] + bb.x);
                smem[(nloc + 1) * 132 + mloc + 8] = rtf32(acc[mf][nf][3] + bb.y);
            }
        }
        __syncthreads();
        const int bb_ = m0 / LK;
        const int kb_ = m0 % LK;
#pragma unroll
        for (int i = 0; i < 32; i++) {
            int n = w * 32 + i;
            float4 vv = *(const float4*)&smem[n * 132 + 4 * l];
            *(float4*)&C[((size_t)(bb_ * DM + n0 + n)) * LK + kb_ + 4 * l] = vv;
        }
    } else {
#pragma unroll
        for (int mf = 0; mf < 4; mf++) {
            int row = m0 + mw + mf * 16 + (l >> 2);
#pragma unroll
            for (int nf = 0; nf < 8; nf++) {
                int col = n0 + nw + nf * 8 + (l & 3) * 2;
                float2 bb = *(const float2*)&bias[col];
                float2 o0, o1;
                o0.x = rtf32(acc[mf][nf][0] + bb.x);
                o0.y = rtf32(acc[mf][nf][1] + bb.y);
                o1.x = rtf32(acc[mf][nf][2] + bb.x);
                o1.y = rtf32(acc[mf][nf][3] + bb.y);
                *(float2*)&C[(size_t)row * DM + col]       = o0;
                *(float2*)&C[(size_t)(row + 8) * DM + col] = o1;
            }
        }
    }
}

// ============================================================================
// Output projection: out = Ao @ Wo^T + bo (Ao pre-rounded; Wo pre-rounded).
// Same 4-warp 64x64 body, no CVT, no RND.
// ============================================================================
__global__ __launch_bounds__(128, 2) void gemm_out_tf32(
    const float* __restrict__ A, const float* __restrict__ B,
    const float* __restrict__ bias, float* __restrict__ C)
{
    extern __shared__ float smem[];
    const uint32_t sbase = s_u32(smem);
    const int tid = threadIdx.x;
    const int m0 = blockIdx.y * 128, n0 = blockIdx.x * 128;
    const int l  = tid & 31, w = tid >> 5;
    const int mw = (w >> 1) * 64, nw = (w & 1) * 64;
    const int lrow = l & 15, lq_ = l >> 4, lx = l & 7;

    float acc[4][8][4];
#pragma unroll
    for (int i = 0; i < 4; i++)
#pragma unroll
        for (int j = 0; j < 8; j++)
#pragma unroll
            for (int r = 0; r < 4; r++) acc[i][j][r] = 0.f;

#define STAGE_O(IT, BUF) do {                                                  \
    uint32_t sA_ = sbase + (BUF) * 32768;                                      \
    uint32_t sB_ = sA_ + 16384;                                                \
    const float* Ag_ = A + (size_t)(m0) * DM + (IT) * 32;                      \
    const float* Bg_ = B + (size_t)(n0) * DM + (IT) * 32;                      \
    _Pragma("unroll")                                                          \
    for (int i_ = 0; i_ < 8; i_++) {                                           \
        int gi_ = tid + i_ * 128;                                              \
        int r_ = gi_ >> 3, g_ = gi_ & 7;                                       \
        CP16(sA_ + r_ * 128 + (((g_ ^ (r_ & 7)) << 4)),                        \
             Ag_ + (size_t)r_ * DM + g_ * 4);                                  \
    }                                                                          \
    _Pragma("unroll")                                                          \
    for (int i_ = 0; i_ < 8; i_++) {                                           \
        int gi_ = tid + i_ * 128;                                              \
        int r_ = gi_ >> 3, g_ = gi_ & 7;                                       \
        CP16(sB_ + r_ * 128 + (((g_ ^ (r_ & 7)) << 4)),                        \
             Bg_ + (size_t)r_ * DM + g_ * 4);                                  \
    }                                                                          \
} while (0)

    STAGE_O(0, 0);
    CPCOMMIT;

    int buf = 0;
    for (int it = 0; it < DM / 32; ++it) {
        if (it + 1 < DM / 32) { STAGE_O(it + 1, buf ^ 1); CPCOMMIT; CPWAIT1; }
        else                  { CPWAIT0; }
        __syncthreads();

        const uint32_t sA = sbase + buf * 32768;
        const uint32_t sB = sA + 16384;
        const uint32_t aAdr0 = sA + (mw + lrow) * 128;
        const uint32_t bAdr0 = sB + (nw + (l & 7)) * 128;

#pragma unroll
        for (int s = 0; s < 4; s += 2) {
            uint32_t bfr[8][4];
#pragma unroll
            for (int nf = 0; nf < 8; nf++) {
                uint32_t ad = bAdr0 + nf * 1024 +
                              (((2 * s + ((l >> 3) & 3)) ^ lx) << 4);
                LDSM4(bfr[nf][0], bfr[nf][1], bfr[nf][2], bfr[nf][3], ad);
            }
#pragma unroll
            for (int ss = 0; ss < 2; ss++) {
                uint32_t a[4][4];
#pragma unroll
                for (int mf = 0; mf < 4; mf++) {
                    uint32_t ad = aAdr0 + mf * 2048 +
                                  (((2 * (s + ss) + lq_) ^ lx) << 4);
                    LDSM4(a[mf][0], a[mf][1], a[mf][2], a[mf][3], ad);
                }
#pragma unroll
                for (int mf = 0; mf < 4; mf++)
#pragma unroll
                    for (int nf = 0; nf < 8; nf++)
                        MMA_TF32(acc[mf][nf], a[mf], bfr[nf][2 * ss], bfr[nf][2 * ss + 1]);
            }
        }
        __syncthreads();
        buf ^= 1;
    }
#undef STAGE_O

#pragma unroll
    for (int mf = 0; mf < 4; mf++) {
        int row = m0 + mw + mf * 16 + (l >> 2);
#pragma unroll
        for (int nf = 0; nf < 8; nf++) {
            int col = n0 + nw + nf * 8 + (l & 3) * 2;
            float2 bb = *(const float2*)&bias[col];
            float2 o0, o1;
            o0.x = acc[mf][nf][0] + bb.x; o0.y = acc[mf][nf][1] + bb.y;
            o1.x = acc[mf][nf][2] + bb.x; o1.y = acc[mf][nf][3] + bb.y;
            *(float2*)&C[(size_t)row * DM + col]       = o0;
            *(float2*)&C[(size_t)(row + 8) * DM + col] = o1;
        }
    }
}

// ============================================================================
// Fused flash attention. CTA: 64 queries, 4 warps, 2 CTAs/SM.
// No-max softmax, branchless (mask selects exp ARGUMENT; exp unconditional).
// ============================================================================
__global__ __launch_bounds__(128, 2) void flash_attn_tf32(
    const float* __restrict__ Qp, const float* __restrict__ Kp,
    const float* __restrict__ Vt, const unsigned short* __restrict__ bm,
    const float* __restrict__ b_table, float* __restrict__ Ao)
{
    extern __shared__ float smem[];
    const uint32_t sb = s_u32(smem);
    const uint32_t sQ = sb;                       // aliased by P after Q consumed
    const uint32_t sKb[2]  = { sb + 16384, sb + 57344 };
    const uint32_t sVb[2]  = { sb + 32768, sb + 73728 };
    const uint32_t sBMb[2] = { sb + 49152, sb + 90112 };
    const uint32_t bmOff[2] = { 49152, 90112 };
    float* btm = smem + 98304 / 4;

    const int tid = threadIdx.x;
    const int h = blockIdx.x, b = blockIdx.z;
    const int m0 = blockIdx.y * 64;
    const int l = tid & 31, w = tid >> 5;
    const int mw = w * 16;
    const int lx = l & 7;

    for (int i = tid; i < VOCAB_B; i += 128) btm[i] = b_table[i * NH + h];

    const float* Qg = Qp + ((size_t)(b * LQ + m0)) * DM + h * DK;
    const float* Kg = Kp + ((size_t)(b * LK)) * DM + h * DK;
    const float* Vg = Vt + ((size_t)(b * DM + h * DK)) * LK;
    const unsigned short* BMg = bm + ((size_t)(b * LQ + m0)) * LK;

#pragma unroll
    for (int i = 0; i < 8; i++) {
        int gi = tid + i * 128;
        int r = gi >> 4, g = gi & 15;
        CP16(sQ + r * 256 + (((g ^ (r & 7)) << 4)), Qg + (size_t)r * DM + g * 4);
    }

#define STAGE_KV(IT, BUF) do {                                                 \
    const float* Ksrc_ = Kg + (size_t)((IT) * 64) * DM;                        \
    const float* Vsrc_ = Vg + (IT) * 64;                                       \
    const unsigned short* Bsrc_ = BMg + (IT) * 64;                             \
    _Pragma("unroll")                                                          \
    for (int i_ = 0; i_ < 8; i_++) {                                           \
        int gi_ = tid + i_ * 128;                                              \
        int r_ = gi_ >> 4, g_ = gi_ & 15;                                      \
        CP16(sKb[BUF] + r_ * 256 + (((g_ ^ (r_ & 7)) << 4)),                   \
             Ksrc_ + (size_t)r_ * DM + g_ * 4);                                \
    }                                                                          \
    _Pragma("unroll")                                                          \
    for (int i_ = 0; i_ < 8; i_++) {                                           \
        int gi_ = tid + i_ * 128;                                              \
        int r_ = gi_ >> 4, g_ = gi_ & 15;                                      \
        CP16(sVb[BUF] + r_ * 256 + (((g_ ^ (r_ & 7)) << 4)),                   \
             Vsrc_ + (size_t)r_ * LK + g_ * 4);                                \
    }                                                                          \
    _Pragma("unroll")                                                          \
    for (int i_ = 0; i_ < 4; i_++) {                                           \
        int gi_ = tid + i_ * 128;                                              \
        int r_ = gi_ >> 3, g_ = gi_ & 7;                                       \
        CP16(sBMb[BUF] + r_ * 128 + (((g_ ^ (r_ & 7)) << 4)),                  \
             Bsrc_ + (size_t)r_ * LK + g_ * 8);                                \
    }                                                                          \
} while (0)

    STAGE_KV(0, 0);
    CPCOMMIT;

    uint32_t aq[8][4];
    float oacc[8][4];
#pragma unroll
    for (int nf = 0; nf < 8; nf++)
#pragma unroll
        for (int r = 0; r < 4; r++) oacc[nf][r] = 0.f;
    float sr0 = 0.f, sr1 = 0.f;

    const int lr = mw + (l >> 2);
    const uint32_t lrx = (uint32_t)(lr & 7);

    int buf = 0;
    for (int it = 0; it < LK / 64; ++it) {
        if (it + 1 < LK / 64) { STAGE_KV(it + 1, buf ^ 1); CPCOMMIT; CPWAIT1; }
        else                  { CPWAIT0; }
        __syncthreads();

        if (it == 0) {
#pragma unroll
            for (int kg = 0; kg < 8; kg++) {
                uint32_t ad = sQ + (mw + (l & 15)) * 256 +
                              (((2 * kg + (l >> 4)) ^ lx) << 4);
                LDSM4(aq[kg][0], aq[kg][1], aq[kg][2], aq[kg][3], ad);
            }
        }

        // ---- S = Q K^T ----
        float sval[8][4];
#pragma unroll
        for (int nf = 0; nf < 8; nf++)
#pragma unroll
            for (int r = 0; r < 4; r++) sval[nf][r] = 0.f;

#pragma unroll
        for (int s = 0; s < 8; s += 2) {
#pragma unroll
            for (int nf = 0; nf < 8; nf++) {
                uint32_t kb[4];
                uint32_t ad = sKb[buf] + (nf * 8 + lx) * 256 +
                              (((2 * s + ((l >> 3) & 3)) ^ lx) << 4);
                LDSM4(kb[0], kb[1], kb[2], kb[3], ad);
                MMA_TF32(sval[nf], aq[s],     kb[0], kb[1]);
                MMA_TF32(sval[nf], aq[s + 1], kb[2], kb[3]);
            }
        }

        // ---- scale + bias gather + mask (SELECT) then unconditional exp ----
        {
            const uint32_t base = bmOff[buf] / 4 + lr * 32 + (l & 3);
            const uint32_t* sm32 = (const uint32_t*)smem;
#pragma unroll
            for (int nf = 0; nf < 8; nf++) {
                uint32_t o = base + (((uint32_t)nf ^ lrx) << 2);
                uint32_t e01 = sm32[o];
                uint32_t e23 = sm32[o + 8 * 32];
                uint32_t e0 = e01 & 0xffffu, e1 = e01 >> 16;
                uint32_t e2 = e23 & 0xffffu, e3 = e23 >> 16;
                float a0 = (e0 & 0x8000u) ? sval[nf][0] * 0.125f + btm[e0 & 0x3ffu] : -1e30f;
                float a1 = (e1 & 0x8000u) ? sval[nf][1] * 0.125f + btm[e1 & 0x3ffu] : -1e30f;
                float a2 = (e2 & 0x8000u) ? sval[nf][2] * 0.125f + btm[e2 & 0x3ffu] : -1e30f;
                float a3 = (e3 & 0x8000u) ? sval[nf][3] * 0.125f + btm[e3 & 0x3ffu] : -1e30f;
                sval[nf][0] = __expf(a0);
                sval[nf][1] = __expf(a1);
                sval[nf][2] = __expf(a2);
                sval[nf][3] = __expf(a3);
                sr0 += sval[nf][0] + sval[nf][1];
                sr1 += sval[nf][2] + sval[nf][3];
            }
        }

        // ---- P -> per-warp patch (aliases this warp's Q rows) ----
        {
            const uint32_t pb = sQ + w * 4096;
            const int rs0 = l >> 2;
            const uint32_t boff = ((l & 1) << 3);
            __syncwarp();
#pragma unroll
            for (int nf = 0; nf < 8; nf++) {
                int g = nf * 2 + ((l & 3) >> 1);
                uint32_t a0 = pb + rs0 * 256 + (((g ^ rs0) << 4)) + boff;
                uint32_t a1 = pb + (rs0 + 8) * 256 + (((g ^ rs0) << 4)) + boff;
                float2 p0 = { sval[nf][0], sval[nf][1] };
                float2 p1 = { sval[nf][2], sval[nf][3] };
                *(float2*)(smem + ((a0 - sb) >> 2)) = p0;
                *(float2*)(smem + ((a1 - sb) >> 2)) = p1;
            }
            __syncwarp();
        }

        uint32_t pa[8][4];
#pragma unroll
        for (int kg = 0; kg < 8; kg++) {
            uint32_t ad = sQ + w * 4096 + (l & 15) * 256 +
                          (((2 * kg + (l >> 4)) ^ lx) << 4);
            LDSM4(pa[kg][0], pa[kg][1], pa[kg][2], pa[kg][3], ad);
            CVT_TF32(pa[kg][0]); CVT_TF32(pa[kg][1]);
            CVT_TF32(pa[kg][2]); CVT_TF32(pa[kg][3]);
        }

        // ---- O += P V ----
#pragma unroll
        for (int s = 0; s < 8; s += 2) {
#pragma unroll
            for (int nf = 0; nf < 8; nf++) {
                uint32_t bv[4];
                uint32_t ad = sVb[buf] + (nf * 8 + lx) * 256 +
                              (((2 * s + ((l >> 3) & 3)) ^ lx) << 4);
                LDSM4(bv[0], bv[1], bv[2], bv[3], ad);
                MMA_TF32(oacc[nf], pa[s],     bv[0], bv[1]);
                MMA_TF32(oacc[nf], pa[s + 1], bv[2], bv[3]);
            }
        }

        __syncthreads();
        buf ^= 1;
    }
#undef STAGE_KV

    // ---- reduce sums across the 4 lanes sharing each row, write O ----
    {
#pragma unroll
        for (int o = 1; o < 4; o <<= 1) {
            sr0 += __shfl_xor_sync(0xffffffffu, sr0, o);
            sr1 += __shfl_xor_sync(0xffffffffu, sr1, o);
        }
        const float i0 = (sr0 > 0.f) ? 1.f / sr0 : 0.f;
        const float i1 = (sr1 > 0.f) ? 1.f / sr1 : 0.f;
        const int r0 = m0 + mw + (l >> 2);
#pragma unroll
        for (int nf = 0; nf < 8; nf++) {
            int col = h * DK + nf * 8 + (l & 3) * 2;
            float2 o0 = { rtf32(oacc[nf][0] * i0), rtf32(oacc[nf][1] * i0) };
            float2 o1 = { rtf32(oacc[nf][2] * i1), rtf32(oacc[nf][3] * i1) };
            *(float2*)&Ao[((size_t)(b * LQ + r0)) * DM + col]     = o0;
            *(float2*)&Ao[((size_t)(b * LQ + r0 + 8)) * DM + col] = o1;
        }
    }
}

// ---------------------------------------------------------------------------
extern "C" void kernel_launch(void* const* d_in, const int* in_sizes, int n_in,
                              void* d_out, int out_size)
{
    const float* q       = (const float*)d_in[0];
    const float* k       = (const float*)d_in[1];
    const float* v       = (const float*)d_in[2];
    const int*   b_idx   = (const int*)  d_in[3];
    const int*   mask    = (const int*)  d_in[4];
    const float* Wq      = (const float*)d_in[5];
    const float* bq      = (const float*)d_in[6];
    const float* Wk      = (const float*)d_in[7];
    const float* bk      = (const float*)d_in[8];
    const float* Wv      = (const float*)d_in[9];
    const float* bv      = (const float*)d_in[10];
    const float* Wo      = (const float*)d_in[11];
    const float* bo      = (const float*)d_in[12];
    const float* b_table = (const float*)d_in[13];
    float* out = (float*)d_out;

    void *Qp_, *Kp_, *Vt_, *Ao_, *bm_, *Wr_;
    cudaGetSymbolAddress(&Qp_, g_Qp);
    cudaGetSymbolAddress(&Kp_, g_Kp);
    cudaGetSymbolAddress(&Vt_, g_Vt);
    cudaGetSymbolAddress(&Ao_, g_Ao);
    cudaGetSymbolAddress(&bm_, g_bm);
    cudaGetSymbolAddress(&Wr_, g_Wr);
    float* Qp = (float*)Qp_;
    float* Kp = (float*)Kp_;
    float* Vt = (float*)Vt_;
    float* Ao = (float*)Ao_;
    float* Wr = (float*)Wr_;
    unsigned short* bm = (unsigned short*)bm_;

    static int attr_set = 0;
    if (!attr_set) {
        cudaFuncSetAttribute((const void*)proj_qkv_tf32,  cudaFuncAttributeMaxDynamicSharedMemorySize, 69632);
        cudaFuncSetAttribute((const void*)gemm_out_tf32,  cudaFuncAttributeMaxDynamicSharedMemorySize, 65536);
        cudaFuncSetAttribute((const void*)flash_attn_tf32, cudaFuncAttributeMaxDynamicSharedMemorySize, 101904);
        attr_set = 1;
    }

    // prep: pack bias/mask + round all weights (one launch each)
    const int NB4 = BSZ * LQ * LK / 4;
    const int NW4 = DM * DM / 4;
    pack_bm_kernel<<<1024, 256>>>((const int4*)b_idx, (const int4*)mask, (ushort4*)bm, NB4);
    round_w4_kernel<<<dim3(64, 4), 256>>>((const float4*)Wq, (const float4*)Wk,
                                          (const float4*)Wv, (const float4*)Wo,
                                          (float4*)Wr, NW4);

    // fused Q/K/V projections: 8 x 144 CTAs in one launch
    proj_qkv_tf32<<<dim3(DM / 128, 144), 128, 69632>>>(
        q, k, v, Wr, bq, bk, bv, Qp, Kp, Vt);

    // fused attention (h fastest for packed bm L2 reuse)
    flash_attn_tf32<<<dim3(NH, LQ / 64, BSZ), 128, 101904>>>(
        Qp, Kp, Vt, bm, b_table, Ao);

    // output projection
    gemm_out_tf32<<<dim3(DM / 128, (BSZ * LQ) / 128), 128, 65536>>>(
        Ao, Wr + 3 * DM * DM, bo, out);
}